// round 1
// baseline (speedup 1.0000x reference)
#include <cuda_runtime.h>
#include <cstdint>
#include <cstddef>

#define NBATCH 2
#define SEQ    2048
#define NH     16
#define HD     64
#define EMB    1024
#define NTOK   (NBATCH*SEQ)      /* 4096 */
#define NPAIR  (NTOK*NH)         /* 65536 token-head pairs */

#define BM 64
#define BN 64
#define PADB 68                  /* padded smem row stride (floats), 16B-aligned, conflict-free */
#define NKT (SEQ/BN)             /* 32 k tiles */

// Scratch (device globals — no allocation allowed)
__device__ float g_q[(size_t)NTOK*EMB];
__device__ float g_k[(size_t)NTOK*EMB];
__device__ float g_v[(size_t)NTOK*EMB];
__device__ float g_attn[(size_t)NTOK*EMB];

// ---------------------------------------------------------------------------
// Projection: q = x_q @ Wq^T, k = x_k @ Wk^T  (per token-head pair, D=64)
// ---------------------------------------------------------------------------
__global__ __launch_bounds__(256) void proj_qk_kernel(
    const float* __restrict__ queries, const float* __restrict__ keys,
    const float* __restrict__ Wq, const float* __restrict__ Wk)
{
    __shared__ float WqT[64*64];
    __shared__ float WkT[64*64];
    __shared__ float xq[16*64];
    __shared__ float xk[16*64];

    int tid = threadIdx.x;
    for (int i = tid; i < 4096; i += 256) {
        int d = i >> 6, e = i & 63;
        WqT[e*64 + d] = Wq[i];
        WkT[e*64 + d] = Wk[i];
    }
    size_t pb = (size_t)blockIdx.x * 16;   // base pair index
    for (int i = tid; i < 1024; i += 256) {
        xq[i] = queries[pb*64 + i];
        xk[i] = keys[pb*64 + i];
    }
    __syncthreads();

    int d  = tid & 63;
    int p0 = tid >> 6;
    #pragma unroll
    for (int rep = 0; rep < 4; rep++) {
        int p = rep*4 + p0;
        float aq = 0.f, ak = 0.f;
        #pragma unroll
        for (int e = 0; e < 64; e++) {
            aq = fmaf(WqT[e*64 + d], xq[p*64 + e], aq);
            ak = fmaf(WkT[e*64 + d], xk[p*64 + e], ak);
        }
        g_q[(pb + p)*64 + d] = aq;
        g_k[(pb + p)*64 + d] = ak;
    }
}

// v = q @ Wv^T  (NOTE: reference uses projected q, not the 'values' input)
__global__ __launch_bounds__(256) void proj_v_kernel(const float* __restrict__ Wv)
{
    __shared__ float WvT[64*64];
    __shared__ float xq[16*64];

    int tid = threadIdx.x;
    for (int i = tid; i < 4096; i += 256) {
        int d = i >> 6, e = i & 63;
        WvT[e*64 + d] = Wv[i];
    }
    size_t pb = (size_t)blockIdx.x * 16;
    for (int i = tid; i < 1024; i += 256) {
        xq[i] = g_q[pb*64 + i];
    }
    __syncthreads();

    int d  = tid & 63;
    int p0 = tid >> 6;
    #pragma unroll
    for (int rep = 0; rep < 4; rep++) {
        int p = rep*4 + p0;
        float av = 0.f;
        #pragma unroll
        for (int e = 0; e < 64; e++) {
            av = fmaf(WvT[e*64 + d], xq[p*64 + e], av);
        }
        g_v[(pb + p)*64 + d] = av;
    }
}

// ---------------------------------------------------------------------------
// Flash-style attention. Block = (qtile, h, n); 256 threads as 16x16, each a
// 4x4 micro-tile. Online softmax with masked entries as exact-zero probs.
// Dynamic smem: q_s[64][PADB] | kp_s[64][PADB] (k tile, overlaid by P tile)
//             | v_s[64][PADB] | mask_s[64]
// ---------------------------------------------------------------------------
#define ATTN_SMEM_BYTES ((3*64*PADB + 64)*4)

__global__ __launch_bounds__(256) void attn_kernel(const int* __restrict__ mask)
{
    extern __shared__ float sm[];
    float* q_s    = sm;
    float* kp_s   = sm + 64*PADB;
    float* v_s    = sm + 2*64*PADB;
    int*   mask_s = (int*)(sm + 3*64*PADB);

    int tid = threadIdx.x;
    int tx = tid & 15, ty = tid >> 4;
    int n = blockIdx.z, h = blockIdx.y, qt = blockIdx.x;

    // Load Q tile transposed: q_s[d][r]
    const float* qg = g_q + ((size_t)(n*SEQ + qt*BM)*NH + h)*HD;
    for (int idx = tid; idx < 64*16; idx += 256) {
        int r = idx >> 4, d4 = idx & 15;
        float4 v4 = *(const float4*)(qg + (size_t)r*EMB + d4*4);
        q_s[(d4*4+0)*PADB + r] = v4.x;
        q_s[(d4*4+1)*PADB + r] = v4.y;
        q_s[(d4*4+2)*PADB + r] = v4.z;
        q_s[(d4*4+3)*PADB + r] = v4.w;
    }

    float m_run[4], l_run[4], o_acc[4][4];
    #pragma unroll
    for (int i = 0; i < 4; i++) {
        m_run[i] = -1e30f; l_run[i] = 0.f;
        #pragma unroll
        for (int j = 0; j < 4; j++) o_acc[i][j] = 0.f;
    }

    const float INV_SQRT_E = 0.03125f;   // 1/sqrt(1024)

    for (int kt = 0; kt < NKT; kt++) {
        const float* kg = g_k + ((size_t)(n*SEQ + kt*BN)*NH + h)*HD;
        const float* vg = g_v + ((size_t)(n*SEQ + kt*BN)*NH + h)*HD;
        // k transposed into kp_s[d][c]; v straight into v_s[c][d]
        for (int idx = tid; idx < 64*16; idx += 256) {
            int c = idx >> 4, d4 = idx & 15;
            float4 kv = *(const float4*)(kg + (size_t)c*EMB + d4*4);
            kp_s[(d4*4+0)*PADB + c] = kv.x;
            kp_s[(d4*4+1)*PADB + c] = kv.y;
            kp_s[(d4*4+2)*PADB + c] = kv.z;
            kp_s[(d4*4+3)*PADB + c] = kv.w;
            float4 vv = *(const float4*)(vg + (size_t)c*EMB + d4*4);
            *(float4*)(v_s + c*PADB + d4*4) = vv;
        }
        if (tid < BN) mask_s[tid] = mask[n*SEQ + kt*BN + tid];
        __syncthreads();

        // --- S = Q K^T (micro-tile) ---
        float acc[4][4];
        #pragma unroll
        for (int i = 0; i < 4; i++)
            #pragma unroll
            for (int j = 0; j < 4; j++) acc[i][j] = 0.f;

        #pragma unroll
        for (int e = 0; e < 64; e++) {
            float4 qv = *(const float4*)(q_s  + e*PADB + ty*4);
            float4 kv = *(const float4*)(kp_s + e*PADB + tx*4);
            float qr[4] = {qv.x, qv.y, qv.z, qv.w};
            float kc[4] = {kv.x, kv.y, kv.z, kv.w};
            #pragma unroll
            for (int i = 0; i < 4; i++)
                #pragma unroll
                for (int j = 0; j < 4; j++)
                    acc[i][j] = fmaf(qr[i], kc[j], acc[i][j]);
        }

        // --- online softmax ---
        bool um[4];
        #pragma unroll
        for (int j = 0; j < 4; j++) um[j] = (mask_s[tx*4 + j] != 0);

        #pragma unroll
        for (int i = 0; i < 4; i++) {
            float rm = -1e30f;
            #pragma unroll
            for (int j = 0; j < 4; j++) {
                if (um[j]) {
                    float s = acc[i][j] * INV_SQRT_E;
                    acc[i][j] = s;
                    rm = fmaxf(rm, s);
                }
            }
            #pragma unroll
            for (int o = 8; o >= 1; o >>= 1)
                rm = fmaxf(rm, __shfl_xor_sync(0xffffffffu, rm, o));
            float mn = fmaxf(m_run[i], rm);
            float fi = __expf(m_run[i] - mn);
            float sum = 0.f;
            #pragma unroll
            for (int j = 0; j < 4; j++) {
                float p = um[j] ? __expf(acc[i][j] - mn) : 0.f;
                acc[i][j] = p;
                sum += p;
            }
            #pragma unroll
            for (int o = 8; o >= 1; o >>= 1)
                sum += __shfl_xor_sync(0xffffffffu, sum, o);
            l_run[i] = l_run[i] * fi + sum;
            m_run[i] = mn;
            #pragma unroll
            for (int j = 0; j < 4; j++) o_acc[i][j] *= fi;
        }

        __syncthreads();   // everyone done reading k tile
        // store P transposed into kp_s: p_s[c][r]
        #pragma unroll
        for (int i = 0; i < 4; i++)
            #pragma unroll
            for (int j = 0; j < 4; j++)
                kp_s[(tx*4 + j)*PADB + ty*4 + i] = acc[i][j];
        __syncthreads();

        // --- O += P V ---
        #pragma unroll
        for (int c = 0; c < 64; c++) {
            float4 pv = *(const float4*)(kp_s + c*PADB + ty*4);
            float4 vv = *(const float4*)(v_s  + c*PADB + tx*4);
            float pr[4] = {pv.x, pv.y, pv.z, pv.w};
            float vd[4] = {vv.x, vv.y, vv.z, vv.w};
            #pragma unroll
            for (int i = 0; i < 4; i++)
                #pragma unroll
                for (int j = 0; j < 4; j++)
                    o_acc[i][j] = fmaf(pr[i], vd[j], o_acc[i][j]);
        }
        __syncthreads();   // before next iter overwrites k/v/p tiles
    }

    // normalize + write out (layout (N,L,H,D) == (N,L,E) flat)
    float* og = g_attn + ((size_t)(n*SEQ + qt*BM)*NH + h)*HD;
    #pragma unroll
    for (int i = 0; i < 4; i++) {
        float inv_l = 1.f / l_run[i];
        float4 r;
        r.x = o_acc[i][0] * inv_l;
        r.y = o_acc[i][1] * inv_l;
        r.z = o_acc[i][2] * inv_l;
        r.w = o_acc[i][3] * inv_l;
        *(float4*)(og + (size_t)(ty*4 + i)*EMB + tx*4) = r;
    }
}

// ---------------------------------------------------------------------------
// Output projection: out[t][o] = sum_e attn[t][e]*Wo[o][e] + bo[o]
// 64x64 block tile, BK=64, 4x4 micro-tile per thread.
// ---------------------------------------------------------------------------
__global__ __launch_bounds__(256) void out_gemm_kernel(
    const float* __restrict__ Wo, const float* __restrict__ bo,
    float* __restrict__ out)
{
    __shared__ float a_s[64*PADB];   // a_s[e][t]
    __shared__ float w_s[64*PADB];   // w_s[e][o]

    int tid = threadIdx.x;
    int tx = tid & 15, ty = tid >> 4;
    int bt = blockIdx.x;   // token tile (64 tokens)
    int bq = blockIdx.y;   // output tile (64 outs)

    float acc[4][4];
    #pragma unroll
    for (int i = 0; i < 4; i++)
        #pragma unroll
        for (int j = 0; j < 4; j++) acc[i][j] = 0.f;

    for (int kb = 0; kb < EMB/64; kb++) {
        for (int idx = tid; idx < 64*16; idx += 256) {
            int r = idx >> 4, e4 = idx & 15;
            float4 av = *(const float4*)(g_attn + (size_t)(bt*64 + r)*EMB + kb*64 + e4*4);
            a_s[(e4*4+0)*PADB + r] = av.x;
            a_s[(e4*4+1)*PADB + r] = av.y;
            a_s[(e4*4+2)*PADB + r] = av.z;
            a_s[(e4*4+3)*PADB + r] = av.w;
            float4 wv = *(const float4*)(Wo + (size_t)(bq*64 + r)*EMB + kb*64 + e4*4);
            w_s[(e4*4+0)*PADB + r] = wv.x;
            w_s[(e4*4+1)*PADB + r] = wv.y;
            w_s[(e4*4+2)*PADB + r] = wv.z;
            w_s[(e4*4+3)*PADB + r] = wv.w;
        }
        __syncthreads();
        #pragma unroll
        for (int e = 0; e < 64; e++) {
            float4 av = *(const float4*)(a_s + e*PADB + ty*4);
            float4 wv = *(const float4*)(w_s + e*PADB + tx*4);
            float ar[4] = {av.x, av.y, av.z, av.w};
            float wc[4] = {wv.x, wv.y, wv.z, wv.w};
            #pragma unroll
            for (int i = 0; i < 4; i++)
                #pragma unroll
                for (int j = 0; j < 4; j++)
                    acc[i][j] = fmaf(ar[i], wc[j], acc[i][j]);
        }
        __syncthreads();
    }

    int obase = bq*64 + tx*4;
    float4 b4 = *(const float4*)(bo + obase);
    #pragma unroll
    for (int i = 0; i < 4; i++) {
        float4 r;
        r.x = acc[i][0] + b4.x;
        r.y = acc[i][1] + b4.y;
        r.z = acc[i][2] + b4.z;
        r.w = acc[i][3] + b4.w;
        *(float4*)(out + (size_t)(bt*64 + ty*4 + i)*EMB + obase) = r;
    }
}

// ---------------------------------------------------------------------------
extern "C" void kernel_launch(void* const* d_in, const int* in_sizes, int n_in,
                              void* d_out, int out_size)
{
    const float* keys    = (const float*)d_in[0];
    const float* queries = (const float*)d_in[1];
    /* values d_in[2] unused by the reference math */
    const int*   mask    = (const int*)d_in[3];
    const float* Wk      = (const float*)d_in[4];
    const float* Wq      = (const float*)d_in[5];
    const float* Wv      = (const float*)d_in[6];
    const float* Wo      = (const float*)d_in[7];
    const float* bo      = (const float*)d_in[8];
    float* out = (float*)d_out;

    // host-side, not a stream op: safe under graph capture; idempotent
    cudaFuncSetAttribute(attn_kernel,
                         cudaFuncAttributeMaxDynamicSharedMemorySize,
                         ATTN_SMEM_BYTES);

    proj_qk_kernel<<<NPAIR/16, 256>>>(queries, keys, Wq, Wk);
    proj_v_kernel<<<NPAIR/16, 256>>>(Wv);

    dim3 ag(SEQ/BM, NH, NBATCH);
    attn_kernel<<<ag, 256, ATTN_SMEM_BYTES>>>(mask);

    dim3 gg(NTOK/64, EMB/64);
    out_gemm_kernel<<<gg, 256>>>(Wo, bo, out);
}

// round 2
// speedup vs baseline: 3.3015x; 3.3015x over previous
#include <cuda_runtime.h>
#include <cuda_fp16.h>
#include <cstdint>
#include <cstddef>

#define NBATCH 2
#define SEQ    2048
#define NH     16
#define HD     64
#define EMB    1024
#define NTOK   (NBATCH*SEQ)      /* 4096 */
#define NPAIR  (NTOK*NH)         /* 65536 token-head pairs */

// Scratch (device globals — no allocation allowed)
__device__ float g_q[(size_t)NTOK*EMB];
__device__ float g_k[(size_t)NTOK*EMB];
__device__ float g_v[(size_t)NTOK*EMB];
__device__ float g_attn[(size_t)NTOK*EMB];

// ---------------------------------------------------------------------------
// helpers
// ---------------------------------------------------------------------------
__device__ __forceinline__ float f2tf32(float x) {
    uint32_t u;
    asm("cvt.rna.tf32.f32 %0, %1;" : "=r"(u) : "f"(x));
    return __uint_as_float(u);
}

__device__ __forceinline__ uint32_t pack_half2(float lo, float hi) {
    uint32_t u;
    asm("cvt.rn.f16x2.f32 %0, %1, %2;" : "=r"(u) : "f"(hi), "f"(lo));
    return u;
}

// D += A * B  (tf32 m16n8k8, row.col)
__device__ __forceinline__ void mma_tf32(float* d,
                                         const uint32_t* a,
                                         uint32_t b0, uint32_t b1) {
    asm volatile(
        "mma.sync.aligned.m16n8k8.row.col.f32.tf32.tf32.f32 "
        "{%0,%1,%2,%3}, {%4,%5,%6,%7}, {%8,%9}, {%0,%1,%2,%3};"
        : "+f"(d[0]), "+f"(d[1]), "+f"(d[2]), "+f"(d[3])
        : "r"(a[0]), "r"(a[1]), "r"(a[2]), "r"(a[3]), "r"(b0), "r"(b1));
}

// D += A * B  (fp16 m16n8k16, row.col, fp32 accum)
__device__ __forceinline__ void mma_f16(float* d,
                                        uint32_t a0, uint32_t a1,
                                        uint32_t a2, uint32_t a3,
                                        uint32_t b0, uint32_t b1) {
    asm volatile(
        "mma.sync.aligned.m16n8k16.row.col.f32.f16.f16.f32 "
        "{%0,%1,%2,%3}, {%4,%5,%6,%7}, {%8,%9}, {%0,%1,%2,%3};"
        : "+f"(d[0]), "+f"(d[1]), "+f"(d[2]), "+f"(d[3])
        : "r"(a0), "r"(a1), "r"(a2), "r"(a3), "r"(b0), "r"(b1));
}

// ---------------------------------------------------------------------------
// Fused projection: q = Xq Wq^T, k = Xk Wk^T, v = q Wv^T
// Block = 64 token-head pairs, 128 threads (4 warps, 16 rows each).
// ---------------------------------------------------------------------------
#define PROJ_SMEM_BYTES (3*64*68*4)

__global__ __launch_bounds__(128) void proj_kernel(
    const float* __restrict__ queries, const float* __restrict__ keys,
    const float* __restrict__ Wq, const float* __restrict__ Wk,
    const float* __restrict__ Wv)
{
    extern __shared__ float sm[];
    float* xq_s = sm;              // 64 x 68
    float* xk_s = sm + 64*68;      // 64 x 68
    float* w_s  = sm + 2*64*68;    // 64 x 68

    int tid  = threadIdx.x;
    int lane = tid & 31, warp = tid >> 5;
    int g = lane >> 2, tig = lane & 3;
    int r0 = warp * 16;
    size_t pb = (size_t)blockIdx.x * 64;

    // stage Xq, Xk, Wq (tf32-converted)
    for (int idx = tid; idx < 64*16; idx += 128) {
        int r = idx >> 4, d4 = idx & 15;
        float4 a = *(const float4*)(queries + (pb + r)*64 + d4*4);
        float4 b = *(const float4*)(keys    + (pb + r)*64 + d4*4);
        float4 w = *(const float4*)(Wq      + (size_t)r*64 + d4*4);
        float* pa = xq_s + r*68 + d4*4;
        float* pk = xk_s + r*68 + d4*4;
        float* pw = w_s  + r*68 + d4*4;
        pa[0]=f2tf32(a.x); pa[1]=f2tf32(a.y); pa[2]=f2tf32(a.z); pa[3]=f2tf32(a.w);
        pk[0]=f2tf32(b.x); pk[1]=f2tf32(b.y); pk[2]=f2tf32(b.z); pk[3]=f2tf32(b.w);
        pw[0]=f2tf32(w.x); pw[1]=f2tf32(w.y); pw[2]=f2tf32(w.z); pw[3]=f2tf32(w.w);
    }
    __syncthreads();

    // preload A frags for xq and xk
    uint32_t aq[8][4], ak[8][4];
    #pragma unroll
    for (int ks = 0; ks < 8; ks++) {
        int k0 = ks*8;
        aq[ks][0] = __float_as_uint(xq_s[(r0+g  )*68 + k0+tig  ]);
        aq[ks][1] = __float_as_uint(xq_s[(r0+g+8)*68 + k0+tig  ]);
        aq[ks][2] = __float_as_uint(xq_s[(r0+g  )*68 + k0+tig+4]);
        aq[ks][3] = __float_as_uint(xq_s[(r0+g+8)*68 + k0+tig+4]);
        ak[ks][0] = __float_as_uint(xk_s[(r0+g  )*68 + k0+tig  ]);
        ak[ks][1] = __float_as_uint(xk_s[(r0+g+8)*68 + k0+tig  ]);
        ak[ks][2] = __float_as_uint(xk_s[(r0+g  )*68 + k0+tig+4]);
        ak[ks][3] = __float_as_uint(xk_s[(r0+g+8)*68 + k0+tig+4]);
    }

    // q = Xq Wq^T
    float cq[8][4];
    #pragma unroll
    for (int nt = 0; nt < 8; nt++) { cq[nt][0]=cq[nt][1]=cq[nt][2]=cq[nt][3]=0.f; }
    #pragma unroll
    for (int ks = 0; ks < 8; ks++) {
        #pragma unroll
        for (int nt = 0; nt < 8; nt++) {
            uint32_t b0 = __float_as_uint(w_s[(nt*8+g)*68 + ks*8+tig  ]);
            uint32_t b1 = __float_as_uint(w_s[(nt*8+g)*68 + ks*8+tig+4]);
            mma_tf32(cq[nt], aq[ks], b0, b1);
        }
    }
    __syncthreads();  // done with Wq in w_s, done reading xq_s

    // write q to gmem, also stash tf32 q into xq_s for the v step; stage Wk
    #pragma unroll
    for (int nt = 0; nt < 8; nt++) {
        #pragma unroll
        for (int i = 0; i < 2; i++) {
            int r = r0 + g + 8*i;
            float2 v2; v2.x = cq[nt][2*i]; v2.y = cq[nt][2*i+1];
            *(float2*)(g_q + (pb + r)*64 + nt*8 + 2*tig) = v2;
            xq_s[r*68 + nt*8 + 2*tig    ] = f2tf32(cq[nt][2*i]);
            xq_s[r*68 + nt*8 + 2*tig + 1] = f2tf32(cq[nt][2*i+1]);
        }
    }
    for (int idx = tid; idx < 64*16; idx += 128) {
        int r = idx >> 4, d4 = idx & 15;
        float4 w = *(const float4*)(Wk + (size_t)r*64 + d4*4);
        float* pw = w_s + r*68 + d4*4;
        pw[0]=f2tf32(w.x); pw[1]=f2tf32(w.y); pw[2]=f2tf32(w.z); pw[3]=f2tf32(w.w);
    }
    __syncthreads();

    // k = Xk Wk^T
    float ck[8][4];
    #pragma unroll
    for (int nt = 0; nt < 8; nt++) { ck[nt][0]=ck[nt][1]=ck[nt][2]=ck[nt][3]=0.f; }
    #pragma unroll
    for (int ks = 0; ks < 8; ks++) {
        #pragma unroll
        for (int nt = 0; nt < 8; nt++) {
            uint32_t b0 = __float_as_uint(w_s[(nt*8+g)*68 + ks*8+tig  ]);
            uint32_t b1 = __float_as_uint(w_s[(nt*8+g)*68 + ks*8+tig+4]);
            mma_tf32(ck[nt], ak[ks], b0, b1);
        }
    }
    #pragma unroll
    for (int nt = 0; nt < 8; nt++) {
        #pragma unroll
        for (int i = 0; i < 2; i++) {
            int r = r0 + g + 8*i;
            float2 v2; v2.x = ck[nt][2*i]; v2.y = ck[nt][2*i+1];
            *(float2*)(g_k + (pb + r)*64 + nt*8 + 2*tig) = v2;
        }
    }
    __syncthreads();  // done with Wk

    // stage Wv
    for (int idx = tid; idx < 64*16; idx += 128) {
        int r = idx >> 4, d4 = idx & 15;
        float4 w = *(const float4*)(Wv + (size_t)r*64 + d4*4);
        float* pw = w_s + r*68 + d4*4;
        pw[0]=f2tf32(w.x); pw[1]=f2tf32(w.y); pw[2]=f2tf32(w.z); pw[3]=f2tf32(w.w);
    }
    __syncthreads();

    // v = q Wv^T  (A frags from stashed tf32 q)
    uint32_t av[8][4];
    #pragma unroll
    for (int ks = 0; ks < 8; ks++) {
        int k0 = ks*8;
        av[ks][0] = __float_as_uint(xq_s[(r0+g  )*68 + k0+tig  ]);
        av[ks][1] = __float_as_uint(xq_s[(r0+g+8)*68 + k0+tig  ]);
        av[ks][2] = __float_as_uint(xq_s[(r0+g  )*68 + k0+tig+4]);
        av[ks][3] = __float_as_uint(xq_s[(r0+g+8)*68 + k0+tig+4]);
    }
    float cv[8][4];
    #pragma unroll
    for (int nt = 0; nt < 8; nt++) { cv[nt][0]=cv[nt][1]=cv[nt][2]=cv[nt][3]=0.f; }
    #pragma unroll
    for (int ks = 0; ks < 8; ks++) {
        #pragma unroll
        for (int nt = 0; nt < 8; nt++) {
            uint32_t b0 = __float_as_uint(w_s[(nt*8+g)*68 + ks*8+tig  ]);
            uint32_t b1 = __float_as_uint(w_s[(nt*8+g)*68 + ks*8+tig+4]);
            mma_tf32(cv[nt], av[ks], b0, b1);
        }
    }
    #pragma unroll
    for (int nt = 0; nt < 8; nt++) {
        #pragma unroll
        for (int i = 0; i < 2; i++) {
            int r = r0 + g + 8*i;
            float2 v2; v2.x = cv[nt][2*i]; v2.y = cv[nt][2*i+1];
            *(float2*)(g_v + (pb + r)*64 + nt*8 + 2*tig) = v2;
        }
    }
}

// ---------------------------------------------------------------------------
// Flash attention with mma.sync.
// Block = (qtile of 128 rows, h, n); 256 threads = 8 warps, each warp owns
// 16 q-rows x full 64 k-cols. S=QK^T in tf32 mma, P.V in fp16 mma (FA2
// fragment reuse). Online softmax in C-fragment registers.
// ---------------------------------------------------------------------------
#define QT 128
#define ATTN_SMEM_FLOATS (QT*68)            /* q staging dominates */
#define ATTN_SMEM_BYTES  (ATTN_SMEM_FLOATS*4)

__global__ __launch_bounds__(256) void attn_kernel(const int* __restrict__ mask)
{
    extern __shared__ float sm[];
    float* k_s    = sm;                         // 64 x 68 tf32
    __half* vT    = (__half*)(sm + 64*68);      // 64(d) x 72(k) fp16
    int*   mask_s = (int*)(sm + 64*68 + 2304);  // 64 ints
    float* q_s    = sm;                         // transient 128 x 68 (overlaps all)

    int tid  = threadIdx.x;
    int lane = tid & 31, warp = tid >> 5;
    int g = lane >> 2, tig = lane & 3;
    int r0 = warp * 16;
    int n = blockIdx.z, h = blockIdx.y, qt = blockIdx.x;

    // ---- stage Q and preload A fragments (tf32) ----
    const float* qg = g_q + ((size_t)(n*SEQ + qt*QT)*NH + h)*HD;
    for (int idx = tid; idx < QT*16; idx += 256) {
        int r = idx >> 4, d4 = idx & 15;
        float4 v4 = *(const float4*)(qg + (size_t)r*EMB + d4*4);
        float* p = q_s + r*68 + d4*4;
        p[0]=f2tf32(v4.x); p[1]=f2tf32(v4.y); p[2]=f2tf32(v4.z); p[3]=f2tf32(v4.w);
    }
    __syncthreads();
    uint32_t qa[8][4];
    #pragma unroll
    for (int ks = 0; ks < 8; ks++) {
        int k0 = ks*8;
        qa[ks][0] = __float_as_uint(q_s[(r0+g  )*68 + k0+tig  ]);
        qa[ks][1] = __float_as_uint(q_s[(r0+g+8)*68 + k0+tig  ]);
        qa[ks][2] = __float_as_uint(q_s[(r0+g  )*68 + k0+tig+4]);
        qa[ks][3] = __float_as_uint(q_s[(r0+g+8)*68 + k0+tig+4]);
    }
    __syncthreads();   // q_s region now reusable for k/v tiles

    float m_run[2] = {-1e30f, -1e30f};
    float l_run[2] = {0.f, 0.f};
    float o[8][4];
    #pragma unroll
    for (int nt = 0; nt < 8; nt++) { o[nt][0]=o[nt][1]=o[nt][2]=o[nt][3]=0.f; }

    const float INV_SQRT_E = 0.03125f;  // 1/sqrt(1024)

    for (int kt = 0; kt < SEQ/64; kt++) {
        const float* kg = g_k + ((size_t)(n*SEQ + kt*64)*NH + h)*HD;
        const float* vg = g_v + ((size_t)(n*SEQ + kt*64)*NH + h)*HD;
        #pragma unroll
        for (int it = 0; it < 4; it++) {
            int idx = tid + it*256;
            int c = idx >> 4, d4 = idx & 15;
            float4 kv = *(const float4*)(kg + (size_t)c*EMB + d4*4);
            float* p = k_s + c*68 + d4*4;
            p[0]=f2tf32(kv.x); p[1]=f2tf32(kv.y); p[2]=f2tf32(kv.z); p[3]=f2tf32(kv.w);
            float4 vv = *(const float4*)(vg + (size_t)c*EMB + d4*4);
            vT[(d4*4+0)*72 + c] = __float2half_rn(vv.x);
            vT[(d4*4+1)*72 + c] = __float2half_rn(vv.y);
            vT[(d4*4+2)*72 + c] = __float2half_rn(vv.z);
            vT[(d4*4+3)*72 + c] = __float2half_rn(vv.w);
        }
        if (tid < 64) mask_s[tid] = mask[n*SEQ + kt*64 + tid];
        __syncthreads();

        // ---- S = Q K^T ----
        float s[8][4];
        #pragma unroll
        for (int nt = 0; nt < 8; nt++) { s[nt][0]=s[nt][1]=s[nt][2]=s[nt][3]=0.f; }
        #pragma unroll
        for (int ks = 0; ks < 8; ks++) {
            #pragma unroll
            for (int nt = 0; nt < 8; nt++) {
                uint32_t b0 = __float_as_uint(k_s[(nt*8+g)*68 + ks*8+tig  ]);
                uint32_t b1 = __float_as_uint(k_s[(nt*8+g)*68 + ks*8+tig+4]);
                mma_tf32(s[nt], qa[ks], b0, b1);
            }
        }

        // ---- online softmax (rows g, g+8; quad shares a row) ----
        bool um0[8], um1[8];
        #pragma unroll
        for (int nt = 0; nt < 8; nt++) {
            um0[nt] = (mask_s[nt*8 + 2*tig    ] != 0);
            um1[nt] = (mask_s[nt*8 + 2*tig + 1] != 0);
        }
        #pragma unroll
        for (int i = 0; i < 2; i++) {
            float rm = -1e30f;
            #pragma unroll
            for (int nt = 0; nt < 8; nt++) {
                if (um0[nt]) { float sv = s[nt][2*i  ]*INV_SQRT_E; s[nt][2*i  ]=sv; rm=fmaxf(rm,sv); }
                if (um1[nt]) { float sv = s[nt][2*i+1]*INV_SQRT_E; s[nt][2*i+1]=sv; rm=fmaxf(rm,sv); }
            }
            rm = fmaxf(rm, __shfl_xor_sync(0xffffffffu, rm, 1));
            rm = fmaxf(rm, __shfl_xor_sync(0xffffffffu, rm, 2));
            float mn = fmaxf(m_run[i], rm);
            float fi = __expf(m_run[i] - mn);
            float sum = 0.f;
            #pragma unroll
            for (int nt = 0; nt < 8; nt++) {
                float p0 = um0[nt] ? __expf(s[nt][2*i  ] - mn) : 0.f;
                float p1 = um1[nt] ? __expf(s[nt][2*i+1] - mn) : 0.f;
                s[nt][2*i] = p0; s[nt][2*i+1] = p1;
                sum += p0 + p1;
            }
            sum += __shfl_xor_sync(0xffffffffu, sum, 1);
            sum += __shfl_xor_sync(0xffffffffu, sum, 2);
            l_run[i] = l_run[i]*fi + sum;
            m_run[i] = mn;
            #pragma unroll
            for (int nt = 0; nt < 8; nt++) { o[nt][2*i] *= fi; o[nt][2*i+1] *= fi; }
        }

        // ---- O += P V  (fp16 mma, P frags straight from S registers) ----
        #pragma unroll
        for (int kc = 0; kc < 4; kc++) {
            uint32_t pa0 = pack_half2(s[2*kc  ][0], s[2*kc  ][1]);
            uint32_t pa1 = pack_half2(s[2*kc  ][2], s[2*kc  ][3]);
            uint32_t pa2 = pack_half2(s[2*kc+1][0], s[2*kc+1][1]);
            uint32_t pa3 = pack_half2(s[2*kc+1][2], s[2*kc+1][3]);
            #pragma unroll
            for (int nt = 0; nt < 8; nt++) {
                uint32_t b0 = *(const uint32_t*)&vT[(nt*8+g)*72 + kc*16 + 2*tig    ];
                uint32_t b1 = *(const uint32_t*)&vT[(nt*8+g)*72 + kc*16 + 2*tig + 8];
                mma_f16(o[nt], pa0, pa1, pa2, pa3, b0, b1);
            }
        }
        __syncthreads();   // before next tile overwrites k_s / vT
    }

    // ---- normalize + write ----
    float* og = g_attn + ((size_t)(n*SEQ + qt*QT)*NH + h)*HD;
    #pragma unroll
    for (int i = 0; i < 2; i++) {
        int r = r0 + g + 8*i;
        float inv_l = 1.f / l_run[i];
        #pragma unroll
        for (int nt = 0; nt < 8; nt++) {
            float2 v2;
            v2.x = o[nt][2*i  ] * inv_l;
            v2.y = o[nt][2*i+1] * inv_l;
            *(float2*)(og + (size_t)r*EMB + nt*8 + 2*tig) = v2;
        }
    }
}

// ---------------------------------------------------------------------------
// Output projection: out = attn @ Wo^T + bo.  128x128 block tile, kblk=32,
// tf32 mma, 8 warps (4m x 2n), warp tile 32x64.
// ---------------------------------------------------------------------------
__global__ __launch_bounds__(256) void out_gemm_kernel(
    const float* __restrict__ Wo, const float* __restrict__ bo,
    float* __restrict__ out)
{
    __shared__ float a_s[128*36];
    __shared__ float w_s[128*36];

    int tid  = threadIdx.x;
    int lane = tid & 31, warp = tid >> 5;
    int g = lane >> 2, tig = lane & 3;
    int warp_m = warp & 3, warp_n = warp >> 2;
    int r0 = warp_m * 32;     // warp row base within 128
    int c0 = warp_n * 64;     // warp col base within 128
    int bt = blockIdx.x;      // token tile (128 tokens)
    int bq = blockIdx.y;      // out-col tile (128 outs)

    float acc[2][8][4];
    #pragma unroll
    for (int mt = 0; mt < 2; mt++)
        #pragma unroll
        for (int nt = 0; nt < 8; nt++)
            acc[mt][nt][0]=acc[mt][nt][1]=acc[mt][nt][2]=acc[mt][nt][3]=0.f;

    for (int kb = 0; kb < EMB/32; kb++) {
        #pragma unroll
        for (int it = 0; it < 4; it++) {
            int idx = tid + it*256;          // 0..1023
            int r = idx >> 3, e4 = idx & 7;
            float4 a = *(const float4*)(g_attn + (size_t)(bt*128 + r)*EMB + kb*32 + e4*4);
            float* pa = a_s + r*36 + e4*4;
            pa[0]=f2tf32(a.x); pa[1]=f2tf32(a.y); pa[2]=f2tf32(a.z); pa[3]=f2tf32(a.w);
            float4 w = *(const float4*)(Wo + (size_t)(bq*128 + r)*EMB + kb*32 + e4*4);
            float* pw = w_s + r*36 + e4*4;
            pw[0]=f2tf32(w.x); pw[1]=f2tf32(w.y); pw[2]=f2tf32(w.z); pw[3]=f2tf32(w.w);
        }
        __syncthreads();

        #pragma unroll
        for (int ks = 0; ks < 4; ks++) {
            int k0 = ks*8;
            uint32_t a0[4], a1[4];
            a0[0] = __float_as_uint(a_s[(r0+g   )*36 + k0+tig  ]);
            a0[1] = __float_as_uint(a_s[(r0+g+8 )*36 + k0+tig  ]);
            a0[2] = __float_as_uint(a_s[(r0+g   )*36 + k0+tig+4]);
            a0[3] = __float_as_uint(a_s[(r0+g+8 )*36 + k0+tig+4]);
            a1[0] = __float_as_uint(a_s[(r0+g+16)*36 + k0+tig  ]);
            a1[1] = __float_as_uint(a_s[(r0+g+24)*36 + k0+tig  ]);
            a1[2] = __float_as_uint(a_s[(r0+g+16)*36 + k0+tig+4]);
            a1[3] = __float_as_uint(a_s[(r0+g+24)*36 + k0+tig+4]);
            #pragma unroll
            for (int nt = 0; nt < 8; nt++) {
                uint32_t b0 = __float_as_uint(w_s[(c0+nt*8+g)*36 + k0+tig  ]);
                uint32_t b1 = __float_as_uint(w_s[(c0+nt*8+g)*36 + k0+tig+4]);
                mma_tf32(acc[0][nt], a0, b0, b1);
                mma_tf32(acc[1][nt], a1, b0, b1);
            }
        }
        __syncthreads();
    }

    #pragma unroll
    for (int mt = 0; mt < 2; mt++) {
        #pragma unroll
        for (int i = 0; i < 2; i++) {
            int r = bt*128 + r0 + mt*16 + g + 8*i;
            #pragma unroll
            for (int nt = 0; nt < 8; nt++) {
                int c = bq*128 + c0 + nt*8 + 2*tig;
                float2 b2 = *(const float2*)(bo + c);
                float2 v2;
                v2.x = acc[mt][nt][2*i  ] + b2.x;
                v2.y = acc[mt][nt][2*i+1] + b2.y;
                *(float2*)(out + (size_t)r*EMB + c) = v2;
            }
        }
    }
}

// ---------------------------------------------------------------------------
extern "C" void kernel_launch(void* const* d_in, const int* in_sizes, int n_in,
                              void* d_out, int out_size)
{
    const float* keys    = (const float*)d_in[0];
    const float* queries = (const float*)d_in[1];
    /* values d_in[2] unused by the reference math */
    const int*   mask    = (const int*)d_in[3];
    const float* Wk      = (const float*)d_in[4];
    const float* Wq      = (const float*)d_in[5];
    const float* Wv      = (const float*)d_in[6];
    const float* Wo      = (const float*)d_in[7];
    const float* bo      = (const float*)d_in[8];
    float* out = (float*)d_out;

    cudaFuncSetAttribute(proj_kernel,
                         cudaFuncAttributeMaxDynamicSharedMemorySize,
                         PROJ_SMEM_BYTES);
    cudaFuncSetAttribute(attn_kernel,
                         cudaFuncAttributeMaxDynamicSharedMemorySize,
                         ATTN_SMEM_BYTES);

    proj_kernel<<<NPAIR/64, 128, PROJ_SMEM_BYTES>>>(queries, keys, Wq, Wk, Wv);

    dim3 ag(SEQ/QT, NH, NBATCH);
    attn_kernel<<<ag, 256, ATTN_SMEM_BYTES>>>(mask);

    dim3 gg(NTOK/128, EMB/128);
    out_gemm_kernel<<<gg, 256>>>(Wo, bo, out);
}

// round 3
// speedup vs baseline: 6.3742x; 1.9307x over previous
#include <cuda_runtime.h>
#include <cuda_fp16.h>
#include <cuda_bf16.h>
#include <cstdint>
#include <cstddef>

#define NBATCH 2
#define SEQ    2048
#define NH     16
#define HD     64
#define EMB    1024
#define NTOK   (NBATCH*SEQ)      /* 4096 */
#define NPAIR  (NTOK*NH)         /* 65536 token-head pairs */

// Scratch (device globals — no allocation allowed)
__device__ __nv_bfloat16 g_qh[(size_t)NTOK*EMB];    // pre-scaled by 1/sqrt(EMB)
__device__ __nv_bfloat16 g_kh[(size_t)NTOK*EMB];
__device__ __half        g_vh[(size_t)NTOK*EMB];
__device__ __nv_bfloat16 g_attnh[(size_t)NTOK*EMB];

// ---------------------------------------------------------------------------
// helpers
// ---------------------------------------------------------------------------
__device__ __forceinline__ float f2tf32(float x) {
    uint32_t u;
    asm("cvt.rna.tf32.f32 %0, %1;" : "=r"(u) : "f"(x));
    return __uint_as_float(u);
}
__device__ __forceinline__ uint32_t pack_half2(float lo, float hi) {
    uint32_t u;
    asm("cvt.rn.f16x2.f32 %0, %1, %2;" : "=r"(u) : "f"(hi), "f"(lo));
    return u;
}
__device__ __forceinline__ uint32_t pack_bf16x2(float lo, float hi) {
    uint32_t u;
    asm("cvt.rn.bf16x2.f32 %0, %1, %2;" : "=r"(u) : "f"(hi), "f"(lo));
    return u;
}

__device__ __forceinline__ void mma_tf32(float* d, const uint32_t* a,
                                         uint32_t b0, uint32_t b1) {
    asm volatile(
        "mma.sync.aligned.m16n8k8.row.col.f32.tf32.tf32.f32 "
        "{%0,%1,%2,%3}, {%4,%5,%6,%7}, {%8,%9}, {%0,%1,%2,%3};"
        : "+f"(d[0]), "+f"(d[1]), "+f"(d[2]), "+f"(d[3])
        : "r"(a[0]), "r"(a[1]), "r"(a[2]), "r"(a[3]), "r"(b0), "r"(b1));
}
__device__ __forceinline__ void mma_bf16(float* d,
                                         uint32_t a0, uint32_t a1,
                                         uint32_t a2, uint32_t a3,
                                         uint32_t b0, uint32_t b1) {
    asm volatile(
        "mma.sync.aligned.m16n8k16.row.col.f32.bf16.bf16.f32 "
        "{%0,%1,%2,%3}, {%4,%5,%6,%7}, {%8,%9}, {%0,%1,%2,%3};"
        : "+f"(d[0]), "+f"(d[1]), "+f"(d[2]), "+f"(d[3])
        : "r"(a0), "r"(a1), "r"(a2), "r"(a3), "r"(b0), "r"(b1));
}
__device__ __forceinline__ void mma_f16(float* d,
                                        uint32_t a0, uint32_t a1,
                                        uint32_t a2, uint32_t a3,
                                        uint32_t b0, uint32_t b1) {
    asm volatile(
        "mma.sync.aligned.m16n8k16.row.col.f32.f16.f16.f32 "
        "{%0,%1,%2,%3}, {%4,%5,%6,%7}, {%8,%9}, {%0,%1,%2,%3};"
        : "+f"(d[0]), "+f"(d[1]), "+f"(d[2]), "+f"(d[3])
        : "r"(a0), "r"(a1), "r"(a2), "r"(a3), "r"(b0), "r"(b1));
}

__device__ __forceinline__ void cp16(void* dst_smem, const void* src) {
    uint32_t a = (uint32_t)__cvta_generic_to_shared(dst_smem);
    asm volatile("cp.async.cg.shared.global [%0], [%1], 16;" :: "r"(a), "l"(src));
}
#define CP_COMMIT() asm volatile("cp.async.commit_group;")
#define CP_WAIT0()  asm volatile("cp.async.wait_group 0;")

__device__ __forceinline__ void ldsm_x4_t(uint32_t& r0, uint32_t& r1,
                                          uint32_t& r2, uint32_t& r3,
                                          const void* smem_ptr) {
    uint32_t a = (uint32_t)__cvta_generic_to_shared(smem_ptr);
    asm volatile("ldmatrix.sync.aligned.m8n8.x4.trans.shared.b16 "
                 "{%0,%1,%2,%3}, [%4];"
                 : "=r"(r0), "=r"(r1), "=r"(r2), "=r"(r3) : "r"(a));
}

// ---------------------------------------------------------------------------
// Fused projection (tf32 mma for accuracy): q = Xq Wq^T (scaled by 1/32),
// k = Xk Wk^T, v = q Wv^T.  Block = 64 pairs, 128 threads.
// ---------------------------------------------------------------------------
#define PROJ_SMEM_BYTES (3*64*68*4)

__global__ __launch_bounds__(128) void proj_kernel(
    const float* __restrict__ queries, const float* __restrict__ keys,
    const float* __restrict__ Wq, const float* __restrict__ Wk,
    const float* __restrict__ Wv)
{
    extern __shared__ float sm[];
    float* xq_s = sm;              // 64 x 68
    float* xk_s = sm + 64*68;
    float* w_s  = sm + 2*64*68;

    int tid  = threadIdx.x;
    int lane = tid & 31, warp = tid >> 5;
    int g = lane >> 2, tig = lane & 3;
    int r0 = warp * 16;
    size_t pb = (size_t)blockIdx.x * 64;
    const float SCALE = 0.03125f;   // 1/sqrt(1024)

    for (int idx = tid; idx < 64*16; idx += 128) {
        int r = idx >> 4, d4 = idx & 15;
        float4 a = *(const float4*)(queries + (pb + r)*64 + d4*4);
        float4 b = *(const float4*)(keys    + (pb + r)*64 + d4*4);
        float4 w = *(const float4*)(Wq      + (size_t)r*64 + d4*4);
        float* pa = xq_s + r*68 + d4*4;
        float* pk = xk_s + r*68 + d4*4;
        float* pw = w_s  + r*68 + d4*4;
        pa[0]=f2tf32(a.x); pa[1]=f2tf32(a.y); pa[2]=f2tf32(a.z); pa[3]=f2tf32(a.w);
        pk[0]=f2tf32(b.x); pk[1]=f2tf32(b.y); pk[2]=f2tf32(b.z); pk[3]=f2tf32(b.w);
        pw[0]=f2tf32(w.x); pw[1]=f2tf32(w.y); pw[2]=f2tf32(w.z); pw[3]=f2tf32(w.w);
    }
    __syncthreads();

    uint32_t aq[8][4], ak[8][4];
    #pragma unroll
    for (int ks = 0; ks < 8; ks++) {
        int k0 = ks*8;
        aq[ks][0] = __float_as_uint(xq_s[(r0+g  )*68 + k0+tig  ]);
        aq[ks][1] = __float_as_uint(xq_s[(r0+g+8)*68 + k0+tig  ]);
        aq[ks][2] = __float_as_uint(xq_s[(r0+g  )*68 + k0+tig+4]);
        aq[ks][3] = __float_as_uint(xq_s[(r0+g+8)*68 + k0+tig+4]);
        ak[ks][0] = __float_as_uint(xk_s[(r0+g  )*68 + k0+tig  ]);
        ak[ks][1] = __float_as_uint(xk_s[(r0+g+8)*68 + k0+tig  ]);
        ak[ks][2] = __float_as_uint(xk_s[(r0+g  )*68 + k0+tig+4]);
        ak[ks][3] = __float_as_uint(xk_s[(r0+g+8)*68 + k0+tig+4]);
    }

    // q = Xq Wq^T
    float cq[8][4];
    #pragma unroll
    for (int nt = 0; nt < 8; nt++) { cq[nt][0]=cq[nt][1]=cq[nt][2]=cq[nt][3]=0.f; }
    #pragma unroll
    for (int ks = 0; ks < 8; ks++)
        #pragma unroll
        for (int nt = 0; nt < 8; nt++) {
            uint32_t b0 = __float_as_uint(w_s[(nt*8+g)*68 + ks*8+tig  ]);
            uint32_t b1 = __float_as_uint(w_s[(nt*8+g)*68 + ks*8+tig+4]);
            mma_tf32(cq[nt], aq[ks], b0, b1);
        }
    __syncthreads();

    // write q (bf16, pre-scaled) + stash tf32 q for v; stage Wk
    #pragma unroll
    for (int nt = 0; nt < 8; nt++)
        #pragma unroll
        for (int i = 0; i < 2; i++) {
            int r = r0 + g + 8*i;
            *(uint32_t*)(g_qh + (pb + r)*64 + nt*8 + 2*tig) =
                pack_bf16x2(cq[nt][2*i]*SCALE, cq[nt][2*i+1]*SCALE);
            xq_s[r*68 + nt*8 + 2*tig    ] = f2tf32(cq[nt][2*i]);
            xq_s[r*68 + nt*8 + 2*tig + 1] = f2tf32(cq[nt][2*i+1]);
        }
    for (int idx = tid; idx < 64*16; idx += 128) {
        int r = idx >> 4, d4 = idx & 15;
        float4 w = *(const float4*)(Wk + (size_t)r*64 + d4*4);
        float* pw = w_s + r*68 + d4*4;
        pw[0]=f2tf32(w.x); pw[1]=f2tf32(w.y); pw[2]=f2tf32(w.z); pw[3]=f2tf32(w.w);
    }
    __syncthreads();

    // k = Xk Wk^T
    float ck[8][4];
    #pragma unroll
    for (int nt = 0; nt < 8; nt++) { ck[nt][0]=ck[nt][1]=ck[nt][2]=ck[nt][3]=0.f; }
    #pragma unroll
    for (int ks = 0; ks < 8; ks++)
        #pragma unroll
        for (int nt = 0; nt < 8; nt++) {
            uint32_t b0 = __float_as_uint(w_s[(nt*8+g)*68 + ks*8+tig  ]);
            uint32_t b1 = __float_as_uint(w_s[(nt*8+g)*68 + ks*8+tig+4]);
            mma_tf32(ck[nt], ak[ks], b0, b1);
        }
    #pragma unroll
    for (int nt = 0; nt < 8; nt++)
        #pragma unroll
        for (int i = 0; i < 2; i++) {
            int r = r0 + g + 8*i;
            *(uint32_t*)(g_kh + (pb + r)*64 + nt*8 + 2*tig) =
                pack_bf16x2(ck[nt][2*i], ck[nt][2*i+1]);
        }
    __syncthreads();

    // stage Wv
    for (int idx = tid; idx < 64*16; idx += 128) {
        int r = idx >> 4, d4 = idx & 15;
        float4 w = *(const float4*)(Wv + (size_t)r*64 + d4*4);
        float* pw = w_s + r*68 + d4*4;
        pw[0]=f2tf32(w.x); pw[1]=f2tf32(w.y); pw[2]=f2tf32(w.z); pw[3]=f2tf32(w.w);
    }
    __syncthreads();

    // v = q Wv^T
    uint32_t av[8][4];
    #pragma unroll
    for (int ks = 0; ks < 8; ks++) {
        int k0 = ks*8;
        av[ks][0] = __float_as_uint(xq_s[(r0+g  )*68 + k0+tig  ]);
        av[ks][1] = __float_as_uint(xq_s[(r0+g+8)*68 + k0+tig  ]);
        av[ks][2] = __float_as_uint(xq_s[(r0+g  )*68 + k0+tig+4]);
        av[ks][3] = __float_as_uint(xq_s[(r0+g+8)*68 + k0+tig+4]);
    }
    float cv[8][4];
    #pragma unroll
    for (int nt = 0; nt < 8; nt++) { cv[nt][0]=cv[nt][1]=cv[nt][2]=cv[nt][3]=0.f; }
    #pragma unroll
    for (int ks = 0; ks < 8; ks++)
        #pragma unroll
        for (int nt = 0; nt < 8; nt++) {
            uint32_t b0 = __float_as_uint(w_s[(nt*8+g)*68 + ks*8+tig  ]);
            uint32_t b1 = __float_as_uint(w_s[(nt*8+g)*68 + ks*8+tig+4]);
            mma_tf32(cv[nt], av[ks], b0, b1);
        }
    #pragma unroll
    for (int nt = 0; nt < 8; nt++)
        #pragma unroll
        for (int i = 0; i < 2; i++) {
            int r = r0 + g + 8*i;
            *(uint32_t*)(g_vh + (pb + r)*64 + nt*8 + 2*tig) =
                pack_half2(cv[nt][2*i], cv[nt][2*i+1]);
        }
}

// ---------------------------------------------------------------------------
// Flash attention, bf16/fp16 mma, cp.async double-buffered K/V tiles.
// Block = (128 q rows, h, n), 256 threads = 8 warps x 16 rows.
// smem: q_s bf16 128x72 | k_s bf16 2x64x72 | v_s f16 2x64x72 | mask 2x64
// ---------------------------------------------------------------------------
#define QT 128
#define KSTRIDE 72
#define ATTN_SMEM_BYTES ((128*KSTRIDE + 2*64*KSTRIDE + 2*64*KSTRIDE)*2 + 2*64*4)

__global__ __launch_bounds__(256) void attn_kernel(const int* __restrict__ mask)
{
    extern __shared__ char smem_raw[];
    __nv_bfloat16* q_s = (__nv_bfloat16*)smem_raw;          // 128 x 72
    __nv_bfloat16* k_s = q_s + 128*KSTRIDE;                 // 2 x 64 x 72
    __half*        v_s = (__half*)(k_s + 2*64*KSTRIDE);     // 2 x 64 x 72
    int*        mask_s = (int*)(v_s + 2*64*KSTRIDE);        // 2 x 64

    int tid  = threadIdx.x;
    int lane = tid & 31, warp = tid >> 5;
    int g = lane >> 2, tig = lane & 3;
    int r0 = warp * 16;
    int n = blockIdx.z, h = blockIdx.y, qt = blockIdx.x;

    const __nv_bfloat16* qg = g_qh + ((size_t)(n*SEQ + qt*QT)*NH + h)*HD;
    const __nv_bfloat16* kbase = g_kh + ((size_t)(n*SEQ)*NH + h)*HD;
    const __half*        vbase = g_vh + ((size_t)(n*SEQ)*NH + h)*HD;

    // stage Q (cp.async) + tile 0 K/V, one group
    #pragma unroll
    for (int it = 0; it < 4; it++) {
        int idx = tid + it*256;          // 1024 chunks
        int r = idx >> 3, j = idx & 7;
        cp16(q_s + r*KSTRIDE + j*8, qg + (size_t)r*EMB + j*8);
    }
    #pragma unroll
    for (int it = 0; it < 2; it++) {
        int idx = tid + it*256;          // 512 chunks
        int c = idx >> 3, j = idx & 7;
        cp16(k_s + c*KSTRIDE + j*8, kbase + (size_t)c*EMB + j*8);
        cp16(v_s + c*KSTRIDE + j*8, vbase + (size_t)c*EMB + j*8);
    }
    if (tid < 64) mask_s[tid] = mask[n*SEQ + tid];
    CP_COMMIT();
    CP_WAIT0();
    __syncthreads();

    // Q A-fragments (bf16 m16n8k16): 4 k-steps of 16
    uint32_t qa[4][4];
    #pragma unroll
    for (int ks = 0; ks < 4; ks++) {
        int k0 = ks*16;
        qa[ks][0] = *(const uint32_t*)(q_s + (r0+g  )*KSTRIDE + k0 + 2*tig);
        qa[ks][1] = *(const uint32_t*)(q_s + (r0+g+8)*KSTRIDE + k0 + 2*tig);
        qa[ks][2] = *(const uint32_t*)(q_s + (r0+g  )*KSTRIDE + k0 + 8 + 2*tig);
        qa[ks][3] = *(const uint32_t*)(q_s + (r0+g+8)*KSTRIDE + k0 + 8 + 2*tig);
    }

    // ldmatrix base address (per-lane) for V tiles
    int ldrow = ((lane >> 3) & 1) * 8 + (lane & 7);
    int ldcol = (lane >> 4) * 8;
    const __half* vldm_base = v_s + (size_t)ldrow*KSTRIDE + ldcol;

    float m_run[2] = {-1e30f, -1e30f};
    float l_run[2] = {0.f, 0.f};
    float o[8][4];
    #pragma unroll
    for (int nt = 0; nt < 8; nt++) { o[nt][0]=o[nt][1]=o[nt][2]=o[nt][3]=0.f; }

    for (int kt = 0; kt < SEQ/64; kt++) {
        int cur = kt & 1;
        if (kt > 0) { CP_WAIT0(); __syncthreads(); }

        // prefetch next tile into other buffer (overlaps compute below)
        if (kt + 1 < SEQ/64) {
            int nxt = cur ^ 1;
            const __nv_bfloat16* kg = kbase + (size_t)(kt+1)*64*EMB;
            const __half*        vg = vbase + (size_t)(kt+1)*64*EMB;
            #pragma unroll
            for (int it = 0; it < 2; it++) {
                int idx = tid + it*256;
                int c = idx >> 3, j = idx & 7;
                cp16(k_s + (nxt*64 + c)*KSTRIDE + j*8, kg + (size_t)c*EMB + j*8);
                cp16(v_s + (nxt*64 + c)*KSTRIDE + j*8, vg + (size_t)c*EMB + j*8);
            }
            if (tid < 64) mask_s[nxt*64 + tid] = mask[n*SEQ + (kt+1)*64 + tid];
            CP_COMMIT();
        }

        const __nv_bfloat16* kc_s = k_s + cur*64*KSTRIDE;
        const int* mcur = mask_s + cur*64;

        // ---- S = Q K^T (bf16, already scaled via q) ----
        float s[8][4];
        #pragma unroll
        for (int nt = 0; nt < 8; nt++) { s[nt][0]=s[nt][1]=s[nt][2]=s[nt][3]=0.f; }
        #pragma unroll
        for (int ks = 0; ks < 4; ks++)
            #pragma unroll
            for (int nt = 0; nt < 8; nt++) {
                uint32_t b0 = *(const uint32_t*)(kc_s + (nt*8+g)*KSTRIDE + ks*16 + 2*tig);
                uint32_t b1 = *(const uint32_t*)(kc_s + (nt*8+g)*KSTRIDE + ks*16 + 8 + 2*tig);
                mma_bf16(s[nt], qa[ks][0], qa[ks][1], qa[ks][2], qa[ks][3], b0, b1);
            }

        // ---- online softmax ----
        bool um0[8], um1[8];
        #pragma unroll
        for (int nt = 0; nt < 8; nt++) {
            um0[nt] = (mcur[nt*8 + 2*tig    ] != 0);
            um1[nt] = (mcur[nt*8 + 2*tig + 1] != 0);
        }
        #pragma unroll
        for (int i = 0; i < 2; i++) {
            float rm = -1e30f;
            #pragma unroll
            for (int nt = 0; nt < 8; nt++) {
                if (um0[nt]) rm = fmaxf(rm, s[nt][2*i  ]);
                if (um1[nt]) rm = fmaxf(rm, s[nt][2*i+1]);
            }
            rm = fmaxf(rm, __shfl_xor_sync(0xffffffffu, rm, 1));
            rm = fmaxf(rm, __shfl_xor_sync(0xffffffffu, rm, 2));
            float mn = fmaxf(m_run[i], rm);
            float fi = __expf(m_run[i] - mn);
            float sum = 0.f;
            #pragma unroll
            for (int nt = 0; nt < 8; nt++) {
                float p0 = um0[nt] ? __expf(s[nt][2*i  ] - mn) : 0.f;
                float p1 = um1[nt] ? __expf(s[nt][2*i+1] - mn) : 0.f;
                s[nt][2*i] = p0; s[nt][2*i+1] = p1;
                sum += p0 + p1;
            }
            sum += __shfl_xor_sync(0xffffffffu, sum, 1);
            sum += __shfl_xor_sync(0xffffffffu, sum, 2);
            l_run[i] = l_run[i]*fi + sum;
            m_run[i] = mn;
            #pragma unroll
            for (int nt = 0; nt < 8; nt++) { o[nt][2*i] *= fi; o[nt][2*i+1] *= fi; }
        }

        // ---- O += P V (fp16 mma; V B-frags via ldmatrix.x4.trans) ----
        const __half* vldm = vldm_base + (size_t)cur*64*KSTRIDE;
        #pragma unroll
        for (int kc = 0; kc < 4; kc++) {
            uint32_t pa0 = pack_half2(s[2*kc  ][0], s[2*kc  ][1]);
            uint32_t pa1 = pack_half2(s[2*kc  ][2], s[2*kc  ][3]);
            uint32_t pa2 = pack_half2(s[2*kc+1][0], s[2*kc+1][1]);
            uint32_t pa3 = pack_half2(s[2*kc+1][2], s[2*kc+1][3]);
            #pragma unroll
            for (int ntp = 0; ntp < 4; ntp++) {
                uint32_t b0a, b1a, b0b, b1b;
                ldsm_x4_t(b0a, b1a, b0b, b1b, vldm + (size_t)kc*16*KSTRIDE + ntp*16);
                mma_f16(o[2*ntp  ], pa0, pa1, pa2, pa3, b0a, b1a);
                mma_f16(o[2*ntp+1], pa0, pa1, pa2, pa3, b0b, b1b);
            }
        }
    }

    // ---- normalize + write (bf16) ----
    __nv_bfloat16* og = g_attnh + ((size_t)(n*SEQ + qt*QT)*NH + h)*HD;
    #pragma unroll
    for (int i = 0; i < 2; i++) {
        int r = r0 + g + 8*i;
        float inv_l = 1.f / l_run[i];
        #pragma unroll
        for (int nt = 0; nt < 8; nt++) {
            *(uint32_t*)(og + (size_t)r*EMB + nt*8 + 2*tig) =
                pack_bf16x2(o[nt][2*i]*inv_l, o[nt][2*i+1]*inv_l);
        }
    }
}

// ---------------------------------------------------------------------------
// Output projection: out = attn @ Wo^T + bo. bf16 mma, 128x128 tile, kblk=32.
// 8 warps (4m x 2n), warp tile 32x64.
// ---------------------------------------------------------------------------
__global__ __launch_bounds__(256) void out_gemm_kernel(
    const float* __restrict__ Wo, const float* __restrict__ bo,
    float* __restrict__ out)
{
    __shared__ __nv_bfloat16 a_s[128*40];
    __shared__ __nv_bfloat16 w_s[128*40];

    int tid  = threadIdx.x;
    int lane = tid & 31, warp = tid >> 5;
    int g = lane >> 2, tig = lane & 3;
    int warp_m = warp & 3, warp_n = warp >> 2;
    int r0 = warp_m * 32;
    int c0 = warp_n * 64;
    int bt = blockIdx.x;
    int bq = blockIdx.y;

    const __nv_bfloat16* gA = g_attnh + (size_t)bt*128*EMB;

    float acc[2][8][4];
    #pragma unroll
    for (int mt = 0; mt < 2; mt++)
        #pragma unroll
        for (int nt = 0; nt < 8; nt++)
            acc[mt][nt][0]=acc[mt][nt][1]=acc[mt][nt][2]=acc[mt][nt][3]=0.f;

    for (int kb = 0; kb < EMB/32; kb++) {
        // A: cp.async bf16 directly
        #pragma unroll
        for (int it = 0; it < 2; it++) {
            int idx = tid + it*256;        // 512 chunks
            int r = idx >> 2, j = idx & 3;
            cp16(a_s + r*40 + j*8, gA + (size_t)r*EMB + kb*32 + j*8);
        }
        CP_COMMIT();
        // W: fp32 load + cvt to bf16
        #pragma unroll
        for (int it = 0; it < 4; it++) {
            int idx = tid + it*256;        // 1024 float4
            int r = idx >> 3, j = idx & 7;
            float4 w = *(const float4*)(Wo + (size_t)(bq*128 + r)*EMB + kb*32 + j*4);
            uint2 p;
            p.x = pack_bf16x2(w.x, w.y);
            p.y = pack_bf16x2(w.z, w.w);
            *(uint2*)(w_s + r*40 + j*4) = p;
        }
        CP_WAIT0();
        __syncthreads();

        #pragma unroll
        for (int ks = 0; ks < 2; ks++) {
            int k0 = ks*16;
            uint32_t a0[4], a1[4];
            a0[0] = *(const uint32_t*)(a_s + (r0+g   )*40 + k0 + 2*tig);
            a0[1] = *(const uint32_t*)(a_s + (r0+g+8 )*40 + k0 + 2*tig);
            a0[2] = *(const uint32_t*)(a_s + (r0+g   )*40 + k0 + 8 + 2*tig);
            a0[3] = *(const uint32_t*)(a_s + (r0+g+8 )*40 + k0 + 8 + 2*tig);
            a1[0] = *(const uint32_t*)(a_s + (r0+g+16)*40 + k0 + 2*tig);
            a1[1] = *(const uint32_t*)(a_s + (r0+g+24)*40 + k0 + 2*tig);
            a1[2] = *(const uint32_t*)(a_s + (r0+g+16)*40 + k0 + 8 + 2*tig);
            a1[3] = *(const uint32_t*)(a_s + (r0+g+24)*40 + k0 + 8 + 2*tig);
            #pragma unroll
            for (int nt = 0; nt < 8; nt++) {
                uint32_t b0 = *(const uint32_t*)(w_s + (c0+nt*8+g)*40 + k0 + 2*tig);
                uint32_t b1 = *(const uint32_t*)(w_s + (c0+nt*8+g)*40 + k0 + 8 + 2*tig);
                mma_bf16(acc[0][nt], a0[0], a0[1], a0[2], a0[3], b0, b1);
                mma_bf16(acc[1][nt], a1[0], a1[1], a1[2], a1[3], b0, b1);
            }
        }
        __syncthreads();
    }

    #pragma unroll
    for (int mt = 0; mt < 2; mt++)
        #pragma unroll
        for (int i = 0; i < 2; i++) {
            int r = bt*128 + r0 + mt*16 + g + 8*i;
            #pragma unroll
            for (int nt = 0; nt < 8; nt++) {
                int c = bq*128 + c0 + nt*8 + 2*tig;
                float2 b2 = *(const float2*)(bo + c);
                float2 v2;
                v2.x = acc[mt][nt][2*i  ] + b2.x;
                v2.y = acc[mt][nt][2*i+1] + b2.y;
                *(float2*)(out + (size_t)r*EMB + c) = v2;
            }
        }
}

// ---------------------------------------------------------------------------
extern "C" void kernel_launch(void* const* d_in, const int* in_sizes, int n_in,
                              void* d_out, int out_size)
{
    const float* keys    = (const float*)d_in[0];
    const float* queries = (const float*)d_in[1];
    /* values d_in[2] unused by the reference math */
    const int*   mask    = (const int*)d_in[3];
    const float* Wk      = (const float*)d_in[4];
    const float* Wq      = (const float*)d_in[5];
    const float* Wv      = (const float*)d_in[6];
    const float* Wo      = (const float*)d_in[7];
    const float* bo      = (const float*)d_in[8];
    float* out = (float*)d_out;

    cudaFuncSetAttribute(proj_kernel,
                         cudaFuncAttributeMaxDynamicSharedMemorySize,
                         PROJ_SMEM_BYTES);
    cudaFuncSetAttribute(attn_kernel,
                         cudaFuncAttributeMaxDynamicSharedMemorySize,
                         ATTN_SMEM_BYTES);

    proj_kernel<<<NPAIR/64, 128, PROJ_SMEM_BYTES>>>(queries, keys, Wq, Wk, Wv);

    dim3 ag(SEQ/QT, NH, NBATCH);
    attn_kernel<<<ag, 256, ATTN_SMEM_BYTES>>>(mask);

    dim3 gg(NTOK/128, EMB/128);
    out_gemm_kernel<<<gg, 256>>>(Wo, bo, out);
}

// round 4
// speedup vs baseline: 9.2275x; 1.4476x over previous
#include <cuda_runtime.h>
#include <cuda_fp16.h>
#include <cstdint>
#include <cstddef>

#define NBATCH 2
#define SEQ    2048
#define NH     16
#define HD     64
#define EMB    1024
#define NTOK   (NBATCH*SEQ)      /* 4096 */
#define NPAIR  (NTOK*NH)         /* 65536 token-head pairs */

// q pre-scale: log2(e)/sqrt(EMB) so softmax uses pure ex2
#define QSCALE 0.04508422008715254f

// Scratch (device globals — no allocation allowed)
__device__ __half g_qh[(size_t)NTOK*EMB];     // pre-scaled by log2e/32
__device__ __half g_kh[(size_t)NTOK*EMB];
__device__ __half g_vh[(size_t)NTOK*EMB];
__device__ __half g_attnh[(size_t)NTOK*EMB];
__device__ __half g_wqh[HD*HD];
__device__ __half g_wkh[HD*HD];
__device__ __half g_wvh[HD*HD];
__device__ __half g_woh[(size_t)EMB*EMB];

// ---------------------------------------------------------------------------
// helpers
// ---------------------------------------------------------------------------
__device__ __forceinline__ uint32_t pack_half2(float lo, float hi) {
    uint32_t u;
    asm("cvt.rn.f16x2.f32 %0, %1, %2;" : "=r"(u) : "f"(hi), "f"(lo));
    return u;
}
__device__ __forceinline__ uint32_t hadd2(uint32_t a, uint32_t b) {
    uint32_t d;
    asm("add.rn.f16x2 %0, %1, %2;" : "=r"(d) : "r"(a), "r"(b));
    return d;
}
__device__ __forceinline__ uint32_t ex2_f16x2(uint32_t a) {
    uint32_t d;
    asm("ex2.approx.f16x2 %0, %1;" : "=r"(d) : "r"(a));
    return d;
}
__device__ __forceinline__ void mma_f16(float* d,
                                        uint32_t a0, uint32_t a1,
                                        uint32_t a2, uint32_t a3,
                                        uint32_t b0, uint32_t b1) {
    asm volatile(
        "mma.sync.aligned.m16n8k16.row.col.f32.f16.f16.f32 "
        "{%0,%1,%2,%3}, {%4,%5,%6,%7}, {%8,%9}, {%0,%1,%2,%3};"
        : "+f"(d[0]), "+f"(d[1]), "+f"(d[2]), "+f"(d[3])
        : "r"(a0), "r"(a1), "r"(a2), "r"(a3), "r"(b0), "r"(b1));
}
__device__ __forceinline__ void cp16(void* dst_smem, const void* src) {
    uint32_t a = (uint32_t)__cvta_generic_to_shared(dst_smem);
    asm volatile("cp.async.cg.shared.global [%0], [%1], 16;" :: "r"(a), "l"(src));
}
#define CP_COMMIT() asm volatile("cp.async.commit_group;")
#define CP_WAIT0()  asm volatile("cp.async.wait_group 0;")

__device__ __forceinline__ void ldsm_x4(uint32_t& r0, uint32_t& r1,
                                        uint32_t& r2, uint32_t& r3,
                                        const void* smem_ptr) {
    uint32_t a = (uint32_t)__cvta_generic_to_shared(smem_ptr);
    asm volatile("ldmatrix.sync.aligned.m8n8.x4.shared.b16 "
                 "{%0,%1,%2,%3}, [%4];"
                 : "=r"(r0), "=r"(r1), "=r"(r2), "=r"(r3) : "r"(a));
}
__device__ __forceinline__ void ldsm_x4_t(uint32_t& r0, uint32_t& r1,
                                          uint32_t& r2, uint32_t& r3,
                                          const void* smem_ptr) {
    uint32_t a = (uint32_t)__cvta_generic_to_shared(smem_ptr);
    asm volatile("ldmatrix.sync.aligned.m8n8.x4.trans.shared.b16 "
                 "{%0,%1,%2,%3}, [%4];"
                 : "=r"(r0), "=r"(r1), "=r"(r2), "=r"(r3) : "r"(a));
}

// ---------------------------------------------------------------------------
// Weight conversion prologue (fp32 -> fp16), run once per launch
// ---------------------------------------------------------------------------
__global__ __launch_bounds__(256) void cvt_wo_kernel(const float* __restrict__ Wo)
{
    int idx = blockIdx.x*256 + threadIdx.x;      // 262144 float4s
    float4 w = ((const float4*)Wo)[idx];
    uint2 p;
    p.x = pack_half2(w.x, w.y);
    p.y = pack_half2(w.z, w.w);
    ((uint2*)g_woh)[idx] = p;
}
__global__ __launch_bounds__(256) void cvt_w_small(
    const float* __restrict__ Wq, const float* __restrict__ Wk,
    const float* __restrict__ Wv)
{
    int idx = blockIdx.x*256 + threadIdx.x;      // 4096
    g_wqh[idx] = __float2half_rn(Wq[idx]);
    g_wkh[idx] = __float2half_rn(Wk[idx]);
    g_wvh[idx] = __float2half_rn(Wv[idx]);
}

// ---------------------------------------------------------------------------
// Fused projection (fp16 mma): q = Xq Wq^T (scaled), v = q Wv^T (from frags),
// k = Xk Wk^T.  Block = 128 pairs, 256 threads (8 warps x 16 rows).
// ---------------------------------------------------------------------------
#define PROJ_SMEM_BYTES ((2*128*72 + 3*64*72)*2)

__global__ __launch_bounds__(256) void proj_kernel(
    const float* __restrict__ queries, const float* __restrict__ keys)
{
    extern __shared__ __half psm[];
    __half* xq_s = psm;                 // 128 x 72
    __half* xk_s = psm + 128*72;        // 128 x 72
    __half* wq_s = psm + 2*128*72;      // 64 x 72
    __half* wk_s = wq_s + 64*72;
    __half* wv_s = wk_s + 64*72;

    int tid  = threadIdx.x;
    int lane = tid & 31, warp = tid >> 5;
    int g = lane >> 2, tig = lane & 3;
    int r0 = warp * 16;
    size_t pb = (size_t)blockIdx.x * 128;

    // weights via cp.async (fp16 in gmem)
    #pragma unroll
    for (int it = 0; it < 2; it++) {
        int idx = tid + it*256;          // 512 chunks per W
        int r = idx >> 3, j = idx & 7;
        cp16(wq_s + r*72 + j*8, g_wqh + r*64 + j*8);
        cp16(wk_s + r*72 + j*8, g_wkh + r*64 + j*8);
        cp16(wv_s + r*72 + j*8, g_wvh + r*64 + j*8);
    }
    CP_COMMIT();
    // x: fp32 load + cvt
    #pragma unroll
    for (int it = 0; it < 8; it++) {
        int idx = tid + it*256;          // 2048 float4 per tensor
        int r = idx >> 4, j = idx & 15;
        float4 a = *(const float4*)(queries + (pb + r)*64 + j*4);
        float4 b = *(const float4*)(keys    + (pb + r)*64 + j*4);
        uint2 pa, pk;
        pa.x = pack_half2(a.x, a.y); pa.y = pack_half2(a.z, a.w);
        pk.x = pack_half2(b.x, b.y); pk.y = pack_half2(b.z, b.w);
        *(uint2*)(xq_s + r*72 + j*4) = pa;
        *(uint2*)(xk_s + r*72 + j*4) = pk;
    }
    CP_WAIT0();
    __syncthreads();

    // A fragments
    uint32_t aq[4][4], ak[4][4];
    #pragma unroll
    for (int ks = 0; ks < 4; ks++) {
        int k0 = ks*16;
        aq[ks][0] = *(const uint32_t*)(xq_s + (r0+g  )*72 + k0 + 2*tig);
        aq[ks][1] = *(const uint32_t*)(xq_s + (r0+g+8)*72 + k0 + 2*tig);
        aq[ks][2] = *(const uint32_t*)(xq_s + (r0+g  )*72 + k0 + 8 + 2*tig);
        aq[ks][3] = *(const uint32_t*)(xq_s + (r0+g+8)*72 + k0 + 8 + 2*tig);
        ak[ks][0] = *(const uint32_t*)(xk_s + (r0+g  )*72 + k0 + 2*tig);
        ak[ks][1] = *(const uint32_t*)(xk_s + (r0+g+8)*72 + k0 + 2*tig);
        ak[ks][2] = *(const uint32_t*)(xk_s + (r0+g  )*72 + k0 + 8 + 2*tig);
        ak[ks][3] = *(const uint32_t*)(xk_s + (r0+g+8)*72 + k0 + 8 + 2*tig);
    }

    // q = Xq Wq^T
    float cq[8][4];
    #pragma unroll
    for (int nt = 0; nt < 8; nt++) { cq[nt][0]=cq[nt][1]=cq[nt][2]=cq[nt][3]=0.f; }
    #pragma unroll
    for (int ks = 0; ks < 4; ks++)
        #pragma unroll
        for (int nt = 0; nt < 8; nt++) {
            uint32_t b0 = *(const uint32_t*)(wq_s + (nt*8+g)*72 + ks*16 + 2*tig);
            uint32_t b1 = *(const uint32_t*)(wq_s + (nt*8+g)*72 + ks*16 + 8 + 2*tig);
            mma_f16(cq[nt], aq[ks][0], aq[ks][1], aq[ks][2], aq[ks][3], b0, b1);
        }

    // v = q Wv^T  — A-frags built from q C-frags (no smem round trip)
    float cv[8][4];
    #pragma unroll
    for (int nt = 0; nt < 8; nt++) { cv[nt][0]=cv[nt][1]=cv[nt][2]=cv[nt][3]=0.f; }
    #pragma unroll
    for (int ks = 0; ks < 4; ks++) {
        uint32_t a0 = pack_half2(cq[2*ks  ][0], cq[2*ks  ][1]);
        uint32_t a1 = pack_half2(cq[2*ks  ][2], cq[2*ks  ][3]);
        uint32_t a2 = pack_half2(cq[2*ks+1][0], cq[2*ks+1][1]);
        uint32_t a3 = pack_half2(cq[2*ks+1][2], cq[2*ks+1][3]);
        #pragma unroll
        for (int nt = 0; nt < 8; nt++) {
            uint32_t b0 = *(const uint32_t*)(wv_s + (nt*8+g)*72 + ks*16 + 2*tig);
            uint32_t b1 = *(const uint32_t*)(wv_s + (nt*8+g)*72 + ks*16 + 8 + 2*tig);
            mma_f16(cv[nt], a0, a1, a2, a3, b0, b1);
        }
    }

    // store q (scaled) and v; release their registers before the k GEMM
    #pragma unroll
    for (int nt = 0; nt < 8; nt++)
        #pragma unroll
        for (int i = 0; i < 2; i++) {
            int r = r0 + g + 8*i;
            *(uint32_t*)(g_qh + (pb + r)*64 + nt*8 + 2*tig) =
                pack_half2(cq[nt][2*i]*QSCALE, cq[nt][2*i+1]*QSCALE);
            *(uint32_t*)(g_vh + (pb + r)*64 + nt*8 + 2*tig) =
                pack_half2(cv[nt][2*i], cv[nt][2*i+1]);
        }

    // k = Xk Wk^T
    float ck[8][4];
    #pragma unroll
    for (int nt = 0; nt < 8; nt++) { ck[nt][0]=ck[nt][1]=ck[nt][2]=ck[nt][3]=0.f; }
    #pragma unroll
    for (int ks = 0; ks < 4; ks++)
        #pragma unroll
        for (int nt = 0; nt < 8; nt++) {
            uint32_t b0 = *(const uint32_t*)(wk_s + (nt*8+g)*72 + ks*16 + 2*tig);
            uint32_t b1 = *(const uint32_t*)(wk_s + (nt*8+g)*72 + ks*16 + 8 + 2*tig);
            mma_f16(ck[nt], ak[ks][0], ak[ks][1], ak[ks][2], ak[ks][3], b0, b1);
        }
    #pragma unroll
    for (int nt = 0; nt < 8; nt++)
        #pragma unroll
        for (int i = 0; i < 2; i++) {
            int r = r0 + g + 8*i;
            *(uint32_t*)(g_kh + (pb + r)*64 + nt*8 + 2*tig) =
                pack_half2(ck[nt][2*i], ck[nt][2*i+1]);
        }
}

// ---------------------------------------------------------------------------
// Flash attention, fp16 mma, cp.async double-buffered K/V tiles.
// No max-tracking (|logit| < 1), l computed by ones-column mma.
// Block = (128 q rows, h, n), 256 threads = 8 warps x 16 rows.
// ---------------------------------------------------------------------------
#define QT 128
#define KST 72
#define ATTN_SMEM_BYTES ((128*KST + 2*64*KST + 2*64*KST)*2 + 2*64*4)
#define NEG_INF_F16 0xFC00u

__global__ __launch_bounds__(256) void attn_kernel(const int* __restrict__ mask)
{
    extern __shared__ char smem_raw[];
    __half* q_s = (__half*)smem_raw;          // 128 x 72
    __half* k_s = q_s + 128*KST;              // 2 x 64 x 72
    __half* v_s = k_s + 2*64*KST;             // 2 x 64 x 72
    int* mask_s = (int*)(v_s + 2*64*KST);     // 2 x 64

    int tid  = threadIdx.x;
    int lane = tid & 31, warp = tid >> 5;
    int g = lane >> 2, tig = lane & 3;
    int r0 = warp * 16;
    int n = blockIdx.z, h = blockIdx.y, qt = blockIdx.x;

    const __half* qg    = g_qh + ((size_t)(n*SEQ + qt*QT)*NH + h)*HD;
    const __half* kbase = g_kh + ((size_t)(n*SEQ)*NH + h)*HD;
    const __half* vbase = g_vh + ((size_t)(n*SEQ)*NH + h)*HD;

    // stage Q + tile 0 K/V
    #pragma unroll
    for (int it = 0; it < 4; it++) {
        int idx = tid + it*256;      // 1024 chunks
        int r = idx >> 3, j = idx & 7;
        cp16(q_s + r*KST + j*8, qg + (size_t)r*EMB + j*8);
    }
    #pragma unroll
    for (int it = 0; it < 2; it++) {
        int idx = tid + it*256;      // 512 chunks each
        int c = idx >> 3, j = idx & 7;
        cp16(k_s + c*KST + j*8, kbase + (size_t)c*EMB + j*8);
        cp16(v_s + c*KST + j*8, vbase + (size_t)c*EMB + j*8);
    }
    if (tid < 64) mask_s[tid] = mask[n*SEQ + tid];
    CP_COMMIT();
    CP_WAIT0();
    __syncthreads();

    // Q A-fragments
    uint32_t qa[4][4];
    #pragma unroll
    for (int ks = 0; ks < 4; ks++) {
        int k0 = ks*16;
        qa[ks][0] = *(const uint32_t*)(q_s + (r0+g  )*KST + k0 + 2*tig);
        qa[ks][1] = *(const uint32_t*)(q_s + (r0+g+8)*KST + k0 + 2*tig);
        qa[ks][2] = *(const uint32_t*)(q_s + (r0+g  )*KST + k0 + 8 + 2*tig);
        qa[ks][3] = *(const uint32_t*)(q_s + (r0+g+8)*KST + k0 + 8 + 2*tig);
    }

    // per-lane ldmatrix addresses
    // K (non-trans x4): tiles {nt0 klo, nt0 khi, nt1 klo, nt1 khi}
    int kq_row = (lane & 7) + ((lane >> 4) << 3);     // +8 rows for tiles 2,3
    int kq_col = ((lane >> 3) & 1) * 8;               // +8 k for tiles 1,3
    const __half* kldm_lane = k_s + (size_t)kq_row*KST + kq_col;
    // V (trans x4), same pattern as round 3
    int vrow = ((lane >> 3) & 1) * 8 + (lane & 7);
    int vcol = (lane >> 4) * 8;
    const __half* vldm_lane = v_s + (size_t)vrow*KST + vcol;

    // accumulators: o[0..7] = output cols, o[8] = l (ones-column)
    float o[9][4];
    #pragma unroll
    for (int nt = 0; nt < 9; nt++) { o[nt][0]=o[nt][1]=o[nt][2]=o[nt][3]=0.f; }
    uint32_t ones_b = (g == 0) ? 0x3C003C00u : 0u;

    for (int kt = 0; kt < SEQ/64; kt++) {
        int cur = kt & 1;
        if (kt > 0) { CP_WAIT0(); __syncthreads(); }

        // prefetch next tile
        if (kt + 1 < SEQ/64) {
            int nxt = cur ^ 1;
            const __half* kg = kbase + (size_t)(kt+1)*64*EMB;
            const __half* vg = vbase + (size_t)(kt+1)*64*EMB;
            #pragma unroll
            for (int it = 0; it < 2; it++) {
                int idx = tid + it*256;
                int c = idx >> 3, j = idx & 7;
                cp16(k_s + (nxt*64 + c)*KST + j*8, kg + (size_t)c*EMB + j*8);
                cp16(v_s + (nxt*64 + c)*KST + j*8, vg + (size_t)c*EMB + j*8);
            }
            if (tid < 64) mask_s[nxt*64 + tid] = mask[n*SEQ + (kt+1)*64 + tid];
            CP_COMMIT();
        }

        // ---- S = Q K^T (log2-domain logits; q pre-scaled) ----
        float s[8][4];
        #pragma unroll
        for (int nt = 0; nt < 8; nt++) { s[nt][0]=s[nt][1]=s[nt][2]=s[nt][3]=0.f; }
        const __half* kldm = kldm_lane + (size_t)cur*64*KST;
        #pragma unroll
        for (int ks = 0; ks < 4; ks++)
            #pragma unroll
            for (int ntp = 0; ntp < 4; ntp++) {
                uint32_t b0a, b1a, b0b, b1b;
                ldsm_x4(b0a, b1a, b0b, b1b, kldm + (size_t)ntp*16*KST + ks*16);
                mma_f16(s[2*ntp  ], qa[ks][0], qa[ks][1], qa[ks][2], qa[ks][3], b0a, b1a);
                mma_f16(s[2*ntp+1], qa[ks][0], qa[ks][1], qa[ks][2], qa[ks][3], b0b, b1b);
            }

        // ---- p = 2^(s + bias), bias = 0 / -inf from mask; fp16x2 packed ----
        const int* mcur = mask_s + cur*64;
        uint32_t pp[8][2];
        #pragma unroll
        for (int nt = 0; nt < 8; nt++) {
            uint32_t bias = (mcur[nt*8 + 2*tig    ] ? 0u : NEG_INF_F16)
                          | (mcur[nt*8 + 2*tig + 1] ? 0u : (NEG_INF_F16 << 16));
            pp[nt][0] = ex2_f16x2(hadd2(pack_half2(s[nt][0], s[nt][1]), bias));
            pp[nt][1] = ex2_f16x2(hadd2(pack_half2(s[nt][2], s[nt][3]), bias));
        }

        // ---- O += P V (V via ldmatrix.trans); l via ones-column mma ----
        const __half* vldm = vldm_lane + (size_t)cur*64*KST;
        #pragma unroll
        for (int kc = 0; kc < 4; kc++) {
            uint32_t a0 = pp[2*kc][0], a1 = pp[2*kc][1];
            uint32_t a2 = pp[2*kc+1][0], a3 = pp[2*kc+1][1];
            #pragma unroll
            for (int ntp = 0; ntp < 4; ntp++) {
                uint32_t b0a, b1a, b0b, b1b;
                ldsm_x4_t(b0a, b1a, b0b, b1b, vldm + (size_t)kc*16*KST + ntp*16);
                mma_f16(o[2*ntp  ], a0, a1, a2, a3, b0a, b1a);
                mma_f16(o[2*ntp+1], a0, a1, a2, a3, b0b, b1b);
            }
            mma_f16(o[8], a0, a1, a2, a3, ones_b, ones_b);
        }
    }

    // l lives in col 0 of o[8] (tig==0 lanes); broadcast within quad
    int qbase = lane & ~3;
    float l0 = __shfl_sync(0xffffffffu, o[8][0], qbase);
    float l1 = __shfl_sync(0xffffffffu, o[8][2], qbase);
    float inv0 = 1.f / l0, inv1 = 1.f / l1;

    __half* og = g_attnh + ((size_t)(n*SEQ + qt*QT)*NH + h)*HD;
    #pragma unroll
    for (int nt = 0; nt < 8; nt++) {
        int r = r0 + g;
        *(uint32_t*)(og + (size_t)r*EMB + nt*8 + 2*tig) =
            pack_half2(o[nt][0]*inv0, o[nt][1]*inv0);
        *(uint32_t*)(og + (size_t)(r+8)*EMB + nt*8 + 2*tig) =
            pack_half2(o[nt][2]*inv1, o[nt][3]*inv1);
    }
}

// ---------------------------------------------------------------------------
// Output projection: out = attn @ Wo^T + bo. fp16 mma, 128x128 tile,
// kblk=32, cp.async double-buffered. 8 warps (4m x 2n), warp tile 32x64.
// ---------------------------------------------------------------------------
__global__ __launch_bounds__(256) void out_gemm_kernel(
    const float* __restrict__ bo, float* __restrict__ out)
{
    __shared__ __half a_s[2][128*40];
    __shared__ __half w_s[2][128*40];

    int tid  = threadIdx.x;
    int lane = tid & 31, warp = tid >> 5;
    int g = lane >> 2, tig = lane & 3;
    int warp_m = warp & 3, warp_n = warp >> 2;
    int r0 = warp_m * 32;
    int c0 = warp_n * 64;
    int bt = blockIdx.x;
    int bq = blockIdx.y;

    const __half* gA = g_attnh + (size_t)bt*128*EMB;
    const __half* gW = g_woh   + (size_t)bq*128*EMB;

    float acc[2][8][4];
    #pragma unroll
    for (int mt = 0; mt < 2; mt++)
        #pragma unroll
        for (int nt = 0; nt < 8; nt++)
            acc[mt][nt][0]=acc[mt][nt][1]=acc[mt][nt][2]=acc[mt][nt][3]=0.f;

    // stage 0
    {
        #pragma unroll
        for (int it = 0; it < 2; it++) {
            int idx = tid + it*256;      // 512 chunks each
            int r = idx >> 2, j = idx & 3;
            cp16(&a_s[0][r*40 + j*8], gA + (size_t)r*EMB + j*8);
            cp16(&w_s[0][r*40 + j*8], gW + (size_t)r*EMB + j*8);
        }
        CP_COMMIT();
    }

    for (int kb = 0; kb < EMB/32; kb++) {
        int cur = kb & 1;
        CP_WAIT0();
        __syncthreads();
        if (kb + 1 < EMB/32) {
            int nxt = cur ^ 1;
            #pragma unroll
            for (int it = 0; it < 2; it++) {
                int idx = tid + it*256;
                int r = idx >> 2, j = idx & 3;
                cp16(&a_s[nxt][r*40 + j*8], gA + (size_t)r*EMB + (kb+1)*32 + j*8);
                cp16(&w_s[nxt][r*40 + j*8], gW + (size_t)r*EMB + (kb+1)*32 + j*8);
            }
            CP_COMMIT();
        }

        const __half* ac = a_s[cur];
        const __half* wc = w_s[cur];
        #pragma unroll
        for (int ks = 0; ks < 2; ks++) {
            int k0 = ks*16;
            uint32_t a0[4], a1[4];
            a0[0] = *(const uint32_t*)(ac + (r0+g   )*40 + k0 + 2*tig);
            a0[1] = *(const uint32_t*)(ac + (r0+g+8 )*40 + k0 + 2*tig);
            a0[2] = *(const uint32_t*)(ac + (r0+g   )*40 + k0 + 8 + 2*tig);
            a0[3] = *(const uint32_t*)(ac + (r0+g+8 )*40 + k0 + 8 + 2*tig);
            a1[0] = *(const uint32_t*)(ac + (r0+g+16)*40 + k0 + 2*tig);
            a1[1] = *(const uint32_t*)(ac + (r0+g+24)*40 + k0 + 2*tig);
            a1[2] = *(const uint32_t*)(ac + (r0+g+16)*40 + k0 + 8 + 2*tig);
            a1[3] = *(const uint32_t*)(ac + (r0+g+24)*40 + k0 + 8 + 2*tig);
            #pragma unroll
            for (int nt = 0; nt < 8; nt++) {
                uint32_t b0 = *(const uint32_t*)(wc + (c0+nt*8+g)*40 + k0 + 2*tig);
                uint32_t b1 = *(const uint32_t*)(wc + (c0+nt*8+g)*40 + k0 + 8 + 2*tig);
                mma_f16(acc[0][nt], a0[0], a0[1], a0[2], a0[3], b0, b1);
                mma_f16(acc[1][nt], a1[0], a1[1], a1[2], a1[3], b0, b1);
            }
        }
    }

    #pragma unroll
    for (int mt = 0; mt < 2; mt++)
        #pragma unroll
        for (int i = 0; i < 2; i++) {
            int r = bt*128 + r0 + mt*16 + g + 8*i;
            #pragma unroll
            for (int nt = 0; nt < 8; nt++) {
                int c = bq*128 + c0 + nt*8 + 2*tig;
                float2 b2 = *(const float2*)(bo + c);
                float2 v2;
                v2.x = acc[mt][nt][2*i  ] + b2.x;
                v2.y = acc[mt][nt][2*i+1] + b2.y;
                *(float2*)(out + (size_t)r*EMB + c) = v2;
            }
        }
}

// ---------------------------------------------------------------------------
extern "C" void kernel_launch(void* const* d_in, const int* in_sizes, int n_in,
                              void* d_out, int out_size)
{
    const float* keys    = (const float*)d_in[0];
    const float* queries = (const float*)d_in[1];
    /* values d_in[2] unused by the reference math */
    const int*   mask    = (const int*)d_in[3];
    const float* Wk      = (const float*)d_in[4];
    const float* Wq      = (const float*)d_in[5];
    const float* Wv      = (const float*)d_in[6];
    const float* Wo      = (const float*)d_in[7];
    const float* bo      = (const float*)d_in[8];
    float* out = (float*)d_out;

    cudaFuncSetAttribute(proj_kernel,
                         cudaFuncAttributeMaxDynamicSharedMemorySize,
                         PROJ_SMEM_BYTES);
    cudaFuncSetAttribute(attn_kernel,
                         cudaFuncAttributeMaxDynamicSharedMemorySize,
                         ATTN_SMEM_BYTES);

    cvt_w_small<<<16, 256>>>(Wq, Wk, Wv);
    cvt_wo_kernel<<<1024, 256>>>(Wo);

    proj_kernel<<<NPAIR/128, 256, PROJ_SMEM_BYTES>>>(queries, keys);

    dim3 ag(SEQ/QT, NH, NBATCH);
    attn_kernel<<<ag, 256, ATTN_SMEM_BYTES>>>(mask);

    dim3 gg(NTOK/128, EMB/128);
    out_gemm_kernel<<<gg, 256>>>(bo, out);
}

// round 5
// speedup vs baseline: 9.8630x; 1.0689x over previous
#include <cuda_runtime.h>
#include <cuda_fp16.h>
#include <cstdint>
#include <cstddef>

#define NBATCH 2
#define SEQ    2048
#define NH     16
#define HD     64
#define EMB    1024
#define NTOK   (NBATCH*SEQ)      /* 4096 */
#define NPAIR  (NTOK*NH)         /* 65536 token-head pairs */

// q pre-scale: log2(e)/sqrt(EMB) so softmax uses pure ex2
#define QSCALE 0.04508422008715254f

// Scratch (device globals — no allocation allowed)
__device__ __half g_qh[(size_t)NTOK*EMB];     // pre-scaled by log2e/32
__device__ __half g_kh[(size_t)NTOK*EMB];
__device__ __half g_vh[(size_t)NTOK*EMB];
__device__ __half g_attnh[(size_t)NTOK*EMB];
__device__ __half g_wqh[HD*HD];
__device__ __half g_wkh[HD*HD];
__device__ __half g_wvh[HD*HD];
__device__ __half g_woh[(size_t)EMB*EMB];
__device__ __half g_biash[NTOK];              // 0 or -inf per (n, kpos)

// ---------------------------------------------------------------------------
// helpers
// ---------------------------------------------------------------------------
__device__ __forceinline__ uint32_t pack_half2(float lo, float hi) {
    uint32_t u;
    asm("cvt.rn.f16x2.f32 %0, %1, %2;" : "=r"(u) : "f"(hi), "f"(lo));
    return u;
}
__device__ __forceinline__ uint32_t hadd2(uint32_t a, uint32_t b) {
    uint32_t d;
    asm("add.rn.f16x2 %0, %1, %2;" : "=r"(d) : "r"(a), "r"(b));
    return d;
}
__device__ __forceinline__ uint32_t ex2_f16x2(uint32_t a) {
    uint32_t d;
    asm("ex2.approx.f16x2 %0, %1;" : "=r"(d) : "r"(a));
    return d;
}
__device__ __forceinline__ void mma_f16(float* d,
                                        uint32_t a0, uint32_t a1,
                                        uint32_t a2, uint32_t a3,
                                        uint32_t b0, uint32_t b1) {
    asm volatile(
        "mma.sync.aligned.m16n8k16.row.col.f32.f16.f16.f32 "
        "{%0,%1,%2,%3}, {%4,%5,%6,%7}, {%8,%9}, {%0,%1,%2,%3};"
        : "+f"(d[0]), "+f"(d[1]), "+f"(d[2]), "+f"(d[3])
        : "r"(a0), "r"(a1), "r"(a2), "r"(a3), "r"(b0), "r"(b1));
}
// fp16-accumulator mma: C packed as 2x f16x2 (c0 = row g pair, c1 = row g+8)
__device__ __forceinline__ void mma_s16(uint32_t& c0, uint32_t& c1,
                                        uint32_t a0, uint32_t a1,
                                        uint32_t a2, uint32_t a3,
                                        uint32_t b0, uint32_t b1) {
    asm volatile(
        "mma.sync.aligned.m16n8k16.row.col.f16.f16.f16.f16 "
        "{%0,%1}, {%2,%3,%4,%5}, {%6,%7}, {%0,%1};"
        : "+r"(c0), "+r"(c1)
        : "r"(a0), "r"(a1), "r"(a2), "r"(a3), "r"(b0), "r"(b1));
}
__device__ __forceinline__ void cp16(void* dst_smem, const void* src) {
    uint32_t a = (uint32_t)__cvta_generic_to_shared(dst_smem);
    asm volatile("cp.async.cg.shared.global [%0], [%1], 16;" :: "r"(a), "l"(src));
}
#define CP_COMMIT() asm volatile("cp.async.commit_group;")
#define CP_WAIT0()  asm volatile("cp.async.wait_group 0;")
#define CP_WAIT1()  asm volatile("cp.async.wait_group 1;")

__device__ __forceinline__ void ldsm_x4(uint32_t& r0, uint32_t& r1,
                                        uint32_t& r2, uint32_t& r3,
                                        const void* smem_ptr) {
    uint32_t a = (uint32_t)__cvta_generic_to_shared(smem_ptr);
    asm volatile("ldmatrix.sync.aligned.m8n8.x4.shared.b16 "
                 "{%0,%1,%2,%3}, [%4];"
                 : "=r"(r0), "=r"(r1), "=r"(r2), "=r"(r3) : "r"(a));
}
__device__ __forceinline__ void ldsm_x4_t(uint32_t& r0, uint32_t& r1,
                                          uint32_t& r2, uint32_t& r3,
                                          const void* smem_ptr) {
    uint32_t a = (uint32_t)__cvta_generic_to_shared(smem_ptr);
    asm volatile("ldmatrix.sync.aligned.m8n8.x4.trans.shared.b16 "
                 "{%0,%1,%2,%3}, [%4];"
                 : "=r"(r0), "=r"(r1), "=r"(r2), "=r"(r3) : "r"(a));
}

// ---------------------------------------------------------------------------
// Weight / mask conversion prologue (fp32 -> fp16), run once per launch
// ---------------------------------------------------------------------------
__global__ __launch_bounds__(256) void cvt_wo_kernel(const float* __restrict__ Wo)
{
    int idx = blockIdx.x*256 + threadIdx.x;      // 262144 float4s
    float4 w = ((const float4*)Wo)[idx];
    uint2 p;
    p.x = pack_half2(w.x, w.y);
    p.y = pack_half2(w.z, w.w);
    ((uint2*)g_woh)[idx] = p;
}
__global__ __launch_bounds__(256) void cvt_w_small(
    const float* __restrict__ Wq, const float* __restrict__ Wk,
    const float* __restrict__ Wv, const int* __restrict__ mask)
{
    int idx = blockIdx.x*256 + threadIdx.x;      // 4096
    g_wqh[idx] = __float2half_rn(Wq[idx]);
    g_wkh[idx] = __float2half_rn(Wk[idx]);
    g_wvh[idx] = __float2half_rn(Wv[idx]);
    ((uint16_t*)g_biash)[idx] = mask[idx] ? 0x0000u : 0xFC00u;  // 0 / -inf
}

// ---------------------------------------------------------------------------
// Fused projection (fp16 mma): q = Xq Wq^T (scaled), v = q Wv^T (from frags),
// k = Xk Wk^T.  Block = 128 pairs, 256 threads (8 warps x 16 rows).
// ---------------------------------------------------------------------------
#define PROJ_SMEM_BYTES ((2*128*72 + 3*64*72)*2)

__global__ __launch_bounds__(256) void proj_kernel(
    const float* __restrict__ queries, const float* __restrict__ keys)
{
    extern __shared__ __half psm[];
    __half* xq_s = psm;                 // 128 x 72
    __half* xk_s = psm + 128*72;        // 128 x 72
    __half* wq_s = psm + 2*128*72;      // 64 x 72
    __half* wk_s = wq_s + 64*72;
    __half* wv_s = wk_s + 64*72;

    int tid  = threadIdx.x;
    int lane = tid & 31, warp = tid >> 5;
    int g = lane >> 2, tig = lane & 3;
    int r0 = warp * 16;
    size_t pb = (size_t)blockIdx.x * 128;

    #pragma unroll
    for (int it = 0; it < 2; it++) {
        int idx = tid + it*256;
        int r = idx >> 3, j = idx & 7;
        cp16(wq_s + r*72 + j*8, g_wqh + r*64 + j*8);
        cp16(wk_s + r*72 + j*8, g_wkh + r*64 + j*8);
        cp16(wv_s + r*72 + j*8, g_wvh + r*64 + j*8);
    }
    CP_COMMIT();
    #pragma unroll
    for (int it = 0; it < 8; it++) {
        int idx = tid + it*256;
        int r = idx >> 4, j = idx & 15;
        float4 a = *(const float4*)(queries + (pb + r)*64 + j*4);
        float4 b = *(const float4*)(keys    + (pb + r)*64 + j*4);
        uint2 pa, pk;
        pa.x = pack_half2(a.x, a.y); pa.y = pack_half2(a.z, a.w);
        pk.x = pack_half2(b.x, b.y); pk.y = pack_half2(b.z, b.w);
        *(uint2*)(xq_s + r*72 + j*4) = pa;
        *(uint2*)(xk_s + r*72 + j*4) = pk;
    }
    CP_WAIT0();
    __syncthreads();

    uint32_t aq[4][4], ak[4][4];
    #pragma unroll
    for (int ks = 0; ks < 4; ks++) {
        int k0 = ks*16;
        aq[ks][0] = *(const uint32_t*)(xq_s + (r0+g  )*72 + k0 + 2*tig);
        aq[ks][1] = *(const uint32_t*)(xq_s + (r0+g+8)*72 + k0 + 2*tig);
        aq[ks][2] = *(const uint32_t*)(xq_s + (r0+g  )*72 + k0 + 8 + 2*tig);
        aq[ks][3] = *(const uint32_t*)(xq_s + (r0+g+8)*72 + k0 + 8 + 2*tig);
        ak[ks][0] = *(const uint32_t*)(xk_s + (r0+g  )*72 + k0 + 2*tig);
        ak[ks][1] = *(const uint32_t*)(xk_s + (r0+g+8)*72 + k0 + 2*tig);
        ak[ks][2] = *(const uint32_t*)(xk_s + (r0+g  )*72 + k0 + 8 + 2*tig);
        ak[ks][3] = *(const uint32_t*)(xk_s + (r0+g+8)*72 + k0 + 8 + 2*tig);
    }

    float cq[8][4];
    #pragma unroll
    for (int nt = 0; nt < 8; nt++) { cq[nt][0]=cq[nt][1]=cq[nt][2]=cq[nt][3]=0.f; }
    #pragma unroll
    for (int ks = 0; ks < 4; ks++)
        #pragma unroll
        for (int nt = 0; nt < 8; nt++) {
            uint32_t b0 = *(const uint32_t*)(wq_s + (nt*8+g)*72 + ks*16 + 2*tig);
            uint32_t b1 = *(const uint32_t*)(wq_s + (nt*8+g)*72 + ks*16 + 8 + 2*tig);
            mma_f16(cq[nt], aq[ks][0], aq[ks][1], aq[ks][2], aq[ks][3], b0, b1);
        }

    float cv[8][4];
    #pragma unroll
    for (int nt = 0; nt < 8; nt++) { cv[nt][0]=cv[nt][1]=cv[nt][2]=cv[nt][3]=0.f; }
    #pragma unroll
    for (int ks = 0; ks < 4; ks++) {
        uint32_t a0 = pack_half2(cq[2*ks  ][0], cq[2*ks  ][1]);
        uint32_t a1 = pack_half2(cq[2*ks  ][2], cq[2*ks  ][3]);
        uint32_t a2 = pack_half2(cq[2*ks+1][0], cq[2*ks+1][1]);
        uint32_t a3 = pack_half2(cq[2*ks+1][2], cq[2*ks+1][3]);
        #pragma unroll
        for (int nt = 0; nt < 8; nt++) {
            uint32_t b0 = *(const uint32_t*)(wv_s + (nt*8+g)*72 + ks*16 + 2*tig);
            uint32_t b1 = *(const uint32_t*)(wv_s + (nt*8+g)*72 + ks*16 + 8 + 2*tig);
            mma_f16(cv[nt], a0, a1, a2, a3, b0, b1);
        }
    }

    #pragma unroll
    for (int nt = 0; nt < 8; nt++)
        #pragma unroll
        for (int i = 0; i < 2; i++) {
            int r = r0 + g + 8*i;
            *(uint32_t*)(g_qh + (pb + r)*64 + nt*8 + 2*tig) =
                pack_half2(cq[nt][2*i]*QSCALE, cq[nt][2*i+1]*QSCALE);
            *(uint32_t*)(g_vh + (pb + r)*64 + nt*8 + 2*tig) =
                pack_half2(cv[nt][2*i], cv[nt][2*i+1]);
        }

    float ck[8][4];
    #pragma unroll
    for (int nt = 0; nt < 8; nt++) { ck[nt][0]=ck[nt][1]=ck[nt][2]=ck[nt][3]=0.f; }
    #pragma unroll
    for (int ks = 0; ks < 4; ks++)
        #pragma unroll
        for (int nt = 0; nt < 8; nt++) {
            uint32_t b0 = *(const uint32_t*)(wk_s + (nt*8+g)*72 + ks*16 + 2*tig);
            uint32_t b1 = *(const uint32_t*)(wk_s + (nt*8+g)*72 + ks*16 + 8 + 2*tig);
            mma_f16(ck[nt], ak[ks][0], ak[ks][1], ak[ks][2], ak[ks][3], b0, b1);
        }
    #pragma unroll
    for (int nt = 0; nt < 8; nt++)
        #pragma unroll
        for (int i = 0; i < 2; i++) {
            int r = r0 + g + 8*i;
            *(uint32_t*)(g_kh + (pb + r)*64 + nt*8 + 2*tig) =
                pack_half2(ck[nt][2*i], ck[nt][2*i+1]);
        }
}

// ---------------------------------------------------------------------------
// Flash attention, software-pipelined: per tile t the warp computes
//   S(t+1)  [tensor]  then  PV(t) interleaved with softmax(t+1) [tensor ∥ alu]
// so the softmax bubble hides under PV mma. S uses fp16 accumulators whose
// C-frags feed hadd2+ex2 directly. No max tracking; l via ones-column mma.
// ---------------------------------------------------------------------------
#define QT 128
#define KST 72
#define NKT 32
#define ATTN_SMEM_BYTES ((128*KST + 2*64*KST + 2*64*KST + 2*64)*2)

__global__ __launch_bounds__(256, 2) void attn_kernel()
{
    extern __shared__ char smem_raw[];
    __half* q_s    = (__half*)smem_raw;       // 128 x 72
    __half* k_s    = q_s + 128*KST;           // 2 x 64 x 72
    __half* v_s    = k_s + 2*64*KST;          // 2 x 64 x 72
    __half* bias_s = v_s + 2*64*KST;          // 2 x 64

    int tid  = threadIdx.x;
    int lane = tid & 31, warp = tid >> 5;
    int g = lane >> 2, tig = lane & 3;
    int r0 = warp * 16;
    int n = blockIdx.z, h = blockIdx.y, qt = blockIdx.x;

    const __half* qg    = g_qh + ((size_t)(n*SEQ + qt*QT)*NH + h)*HD;
    const __half* kbase = g_kh + ((size_t)(n*SEQ)*NH + h)*HD;
    const __half* vbase = g_vh + ((size_t)(n*SEQ)*NH + h)*HD;
    const __half* gbias = g_biash + n*SEQ;

    // ---- prolog group 1: Q, K(0), bias(0) ----
    #pragma unroll
    for (int it = 0; it < 4; it++) {
        int idx = tid + it*256;
        int r = idx >> 3, j = idx & 7;
        cp16(q_s + r*KST + j*8, qg + (size_t)r*EMB + j*8);
    }
    #pragma unroll
    for (int it = 0; it < 2; it++) {
        int idx = tid + it*256;
        int c = idx >> 3, j = idx & 7;
        cp16(k_s + c*KST + j*8, kbase + (size_t)c*EMB + j*8);
    }
    if (tid < 8) cp16(bias_s + tid*8, gbias + tid*8);
    CP_COMMIT();
    // ---- prolog group 2: K(1), V(0), bias(1) ----
    #pragma unroll
    for (int it = 0; it < 2; it++) {
        int idx = tid + it*256;
        int c = idx >> 3, j = idx & 7;
        cp16(k_s + (64 + c)*KST + j*8, kbase + (size_t)(64 + c)*EMB + j*8);
        cp16(v_s + c*KST + j*8,        vbase + (size_t)c*EMB + j*8);
    }
    if (tid < 8) cp16(bias_s + 64 + tid*8, gbias + 64 + tid*8);
    CP_COMMIT();

    CP_WAIT1();
    __syncthreads();

    // Q A-fragments
    uint32_t qa[4][4];
    #pragma unroll
    for (int ks = 0; ks < 4; ks++) {
        int k0 = ks*16;
        qa[ks][0] = *(const uint32_t*)(q_s + (r0+g  )*KST + k0 + 2*tig);
        qa[ks][1] = *(const uint32_t*)(q_s + (r0+g+8)*KST + k0 + 2*tig);
        qa[ks][2] = *(const uint32_t*)(q_s + (r0+g  )*KST + k0 + 8 + 2*tig);
        qa[ks][3] = *(const uint32_t*)(q_s + (r0+g+8)*KST + k0 + 8 + 2*tig);
    }

    // per-lane ldmatrix bases
    int kq_row = (lane & 7) + ((lane >> 4) << 3);
    int kq_col = ((lane >> 3) & 1) * 8;
    const __half* kldm_lane = k_s + (size_t)kq_row*KST + kq_col;
    int vrow = ((lane >> 3) & 1) * 8 + (lane & 7);
    int vcol = (lane >> 4) * 8;
    const __half* vldm_lane = v_s + (size_t)vrow*KST + vcol;

    float o[9][4];
    #pragma unroll
    for (int nt = 0; nt < 9; nt++) { o[nt][0]=o[nt][1]=o[nt][2]=o[nt][3]=0.f; }
    uint32_t ones_b = (g == 0) ? 0x3C003C00u : 0u;

    uint32_t pp0[8][2], pp1[8][2];   // p ping-pong (even/odd tiles)

    // ---- S(0) + softmax(0) -> pp0 ----
    {
        uint32_t sc[8][2];
        #pragma unroll
        for (int nt = 0; nt < 8; nt++) { sc[nt][0]=0u; sc[nt][1]=0u; }
        #pragma unroll
        for (int ks = 0; ks < 4; ks++)
            #pragma unroll
            for (int ntp = 0; ntp < 4; ntp++) {
                uint32_t b0a, b1a, b0b, b1b;
                ldsm_x4(b0a, b1a, b0b, b1b, kldm_lane + (size_t)ntp*16*KST + ks*16);
                mma_s16(sc[2*ntp  ][0], sc[2*ntp  ][1],
                        qa[ks][0], qa[ks][1], qa[ks][2], qa[ks][3], b0a, b1a);
                mma_s16(sc[2*ntp+1][0], sc[2*ntp+1][1],
                        qa[ks][0], qa[ks][1], qa[ks][2], qa[ks][3], b0b, b1b);
            }
        #pragma unroll
        for (int nt = 0; nt < 8; nt++) {
            uint32_t bb = *(const uint32_t*)(bias_s + nt*8 + 2*tig);
            pp0[nt][0] = ex2_f16x2(hadd2(sc[nt][0], bb));
            pp0[nt][1] = ex2_f16x2(hadd2(sc[nt][1], bb));
        }
    }

    // ---- pipelined main loop: bodies t = 0..30 ----
#define ATTN_BODY(T, PAR, PPC, PPN)                                           \
    do {                                                                      \
        CP_WAIT0();                                                           \
        __syncthreads();                                                      \
        if ((T) + 2 < NKT) {                                                  \
            const __half* kg2 = kbase + (size_t)((T)+2)*64*EMB;               \
            _Pragma("unroll")                                                 \
            for (int it = 0; it < 2; it++) {                                  \
                int idx = tid + it*256;                                       \
                int c = idx >> 3, j = idx & 7;                                \
                cp16(k_s + ((PAR)*64 + c)*KST + j*8, kg2 + (size_t)c*EMB + j*8); \
            }                                                                 \
            if (tid < 8) cp16(bias_s + (PAR)*64 + tid*8,                      \
                              gbias + ((T)+2)*64 + tid*8);                    \
        }                                                                     \
        {                                                                     \
            const __half* vg1 = vbase + (size_t)((T)+1)*64*EMB;               \
            _Pragma("unroll")                                                 \
            for (int it = 0; it < 2; it++) {                                  \
                int idx = tid + it*256;                                       \
                int c = idx >> 3, j = idx & 7;                                \
                cp16(v_s + ((1-(PAR))*64 + c)*KST + j*8, vg1 + (size_t)c*EMB + j*8); \
            }                                                                 \
        }                                                                     \
        CP_COMMIT();                                                          \
        uint32_t sc[8][2];                                                    \
        _Pragma("unroll")                                                     \
        for (int nt = 0; nt < 8; nt++) { sc[nt][0]=0u; sc[nt][1]=0u; }        \
        const __half* kldm = kldm_lane + (size_t)(1-(PAR))*64*KST;            \
        _Pragma("unroll")                                                     \
        for (int ks = 0; ks < 4; ks++)                                        \
            _Pragma("unroll")                                                 \
            for (int ntp = 0; ntp < 4; ntp++) {                               \
                uint32_t b0a, b1a, b0b, b1b;                                  \
                ldsm_x4(b0a, b1a, b0b, b1b, kldm + (size_t)ntp*16*KST + ks*16); \
                mma_s16(sc[2*ntp  ][0], sc[2*ntp  ][1],                       \
                        qa[ks][0], qa[ks][1], qa[ks][2], qa[ks][3], b0a, b1a);\
                mma_s16(sc[2*ntp+1][0], sc[2*ntp+1][1],                       \
                        qa[ks][0], qa[ks][1], qa[ks][2], qa[ks][3], b0b, b1b);\
            }                                                                 \
        const __half* vldm = vldm_lane + (size_t)(PAR)*64*KST;                \
        const __half* bbn  = bias_s + (1-(PAR))*64;                           \
        _Pragma("unroll")                                                     \
        for (int kc = 0; kc < 4; kc++) {                                      \
            uint32_t bb0 = *(const uint32_t*)(bbn + (2*kc  )*8 + 2*tig);      \
            uint32_t bb1 = *(const uint32_t*)(bbn + (2*kc+1)*8 + 2*tig);      \
            PPN[2*kc  ][0] = ex2_f16x2(hadd2(sc[2*kc  ][0], bb0));            \
            PPN[2*kc  ][1] = ex2_f16x2(hadd2(sc[2*kc  ][1], bb0));            \
            PPN[2*kc+1][0] = ex2_f16x2(hadd2(sc[2*kc+1][0], bb1));            \
            PPN[2*kc+1][1] = ex2_f16x2(hadd2(sc[2*kc+1][1], bb1));            \
            uint32_t a0 = PPC[2*kc][0],   a1 = PPC[2*kc][1];                  \
            uint32_t a2 = PPC[2*kc+1][0], a3 = PPC[2*kc+1][1];                \
            _Pragma("unroll")                                                 \
            for (int ntp = 0; ntp < 4; ntp++) {                               \
                uint32_t b0a, b1a, b0b, b1b;                                  \
                ldsm_x4_t(b0a, b1a, b0b, b1b, vldm + (size_t)kc*16*KST + ntp*16); \
                mma_f16(o[2*ntp  ], a0, a1, a2, a3, b0a, b1a);                \
                mma_f16(o[2*ntp+1], a0, a1, a2, a3, b0b, b1b);                \
            }                                                                 \
            mma_f16(o[8], a0, a1, a2, a3, ones_b, ones_b);                    \
        }                                                                     \
    } while (0)

    for (int t = 0; t < NKT - 1; t += 2) {
        ATTN_BODY(t, 0, pp0, pp1);
        if (t + 1 < NKT - 1) ATTN_BODY(t + 1, 1, pp1, pp0);
    }

    // ---- epilog: PV(31) with pp1, V buffer 1 ----
    {
        CP_WAIT0();
        __syncthreads();
        const __half* vldm = vldm_lane + (size_t)1*64*KST;
        #pragma unroll
        for (int kc = 0; kc < 4; kc++) {
            uint32_t a0 = pp1[2*kc][0],   a1 = pp1[2*kc][1];
            uint32_t a2 = pp1[2*kc+1][0], a3 = pp1[2*kc+1][1];
            #pragma unroll
            for (int ntp = 0; ntp < 4; ntp++) {
                uint32_t b0a, b1a, b0b, b1b;
                ldsm_x4_t(b0a, b1a, b0b, b1b, vldm + (size_t)kc*16*KST + ntp*16);
                mma_f16(o[2*ntp  ], a0, a1, a2, a3, b0a, b1a);
                mma_f16(o[2*ntp+1], a0, a1, a2, a3, b0b, b1b);
            }
            mma_f16(o[8], a0, a1, a2, a3, ones_b, ones_b);
        }
    }

    // l lives in col 0 of o[8] (tig==0 lanes); broadcast within quad
    int qbase = lane & ~3;
    float l0 = __shfl_sync(0xffffffffu, o[8][0], qbase);
    float l1 = __shfl_sync(0xffffffffu, o[8][2], qbase);
    float inv0 = 1.f / l0, inv1 = 1.f / l1;

    __half* og = g_attnh + ((size_t)(n*SEQ + qt*QT)*NH + h)*HD;
    #pragma unroll
    for (int nt = 0; nt < 8; nt++) {
        int r = r0 + g;
        *(uint32_t*)(og + (size_t)r*EMB + nt*8 + 2*tig) =
            pack_half2(o[nt][0]*inv0, o[nt][1]*inv0);
        *(uint32_t*)(og + (size_t)(r+8)*EMB + nt*8 + 2*tig) =
            pack_half2(o[nt][2]*inv1, o[nt][3]*inv1);
    }
}

// ---------------------------------------------------------------------------
// Output projection: out = attn @ Wo^T + bo. fp16 mma, 128x128 tile,
// kblk=32, cp.async double-buffered. 8 warps (4m x 2n), warp tile 32x64.
// ---------------------------------------------------------------------------
__global__ __launch_bounds__(256) void out_gemm_kernel(
    const float* __restrict__ bo, float* __restrict__ out)
{
    __shared__ __half a_s[2][128*40];
    __shared__ __half w_s[2][128*40];

    int tid  = threadIdx.x;
    int lane = tid & 31, warp = tid >> 5;
    int g = lane >> 2, tig = lane & 3;
    int warp_m = warp & 3, warp_n = warp >> 2;
    int r0 = warp_m * 32;
    int c0 = warp_n * 64;
    int bt = blockIdx.x;
    int bq = blockIdx.y;

    const __half* gA = g_attnh + (size_t)bt*128*EMB;
    const __half* gW = g_woh   + (size_t)bq*128*EMB;

    float acc[2][8][4];
    #pragma unroll
    for (int mt = 0; mt < 2; mt++)
        #pragma unroll
        for (int nt = 0; nt < 8; nt++)
            acc[mt][nt][0]=acc[mt][nt][1]=acc[mt][nt][2]=acc[mt][nt][3]=0.f;

    {
        #pragma unroll
        for (int it = 0; it < 2; it++) {
            int idx = tid + it*256;
            int r = idx >> 2, j = idx & 3;
            cp16(&a_s[0][r*40 + j*8], gA + (size_t)r*EMB + j*8);
            cp16(&w_s[0][r*40 + j*8], gW + (size_t)r*EMB + j*8);
        }
        CP_COMMIT();
    }

    for (int kb = 0; kb < EMB/32; kb++) {
        int cur = kb & 1;
        CP_WAIT0();
        __syncthreads();
        if (kb + 1 < EMB/32) {
            int nxt = cur ^ 1;
            #pragma unroll
            for (int it = 0; it < 2; it++) {
                int idx = tid + it*256;
                int r = idx >> 2, j = idx & 3;
                cp16(&a_s[nxt][r*40 + j*8], gA + (size_t)r*EMB + (kb+1)*32 + j*8);
                cp16(&w_s[nxt][r*40 + j*8], gW + (size_t)r*EMB + (kb+1)*32 + j*8);
            }
            CP_COMMIT();
        }

        const __half* ac = a_s[cur];
        const __half* wc = w_s[cur];
        #pragma unroll
        for (int ks = 0; ks < 2; ks++) {
            int k0 = ks*16;
            uint32_t a0[4], a1[4];
            a0[0] = *(const uint32_t*)(ac + (r0+g   )*40 + k0 + 2*tig);
            a0[1] = *(const uint32_t*)(ac + (r0+g+8 )*40 + k0 + 2*tig);
            a0[2] = *(const uint32_t*)(ac + (r0+g   )*40 + k0 + 8 + 2*tig);
            a0[3] = *(const uint32_t*)(ac + (r0+g+8 )*40 + k0 + 8 + 2*tig);
            a1[0] = *(const uint32_t*)(ac + (r0+g+16)*40 + k0 + 2*tig);
            a1[1] = *(const uint32_t*)(ac + (r0+g+24)*40 + k0 + 2*tig);
            a1[2] = *(const uint32_t*)(ac + (r0+g+16)*40 + k0 + 8 + 2*tig);
            a1[3] = *(const uint32_t*)(ac + (r0+g+24)*40 + k0 + 8 + 2*tig);
            #pragma unroll
            for (int nt = 0; nt < 8; nt++) {
                uint32_t b0 = *(const uint32_t*)(wc + (c0+nt*8+g)*40 + k0 + 2*tig);
                uint32_t b1 = *(const uint32_t*)(wc + (c0+nt*8+g)*40 + k0 + 8 + 2*tig);
                mma_f16(acc[0][nt], a0[0], a0[1], a0[2], a0[3], b0, b1);
                mma_f16(acc[1][nt], a1[0], a1[1], a1[2], a1[3], b0, b1);
            }
        }
    }

    #pragma unroll
    for (int mt = 0; mt < 2; mt++)
        #pragma unroll
        for (int i = 0; i < 2; i++) {
            int r = bt*128 + r0 + mt*16 + g + 8*i;
            #pragma unroll
            for (int nt = 0; nt < 8; nt++) {
                int c = bq*128 + c0 + nt*8 + 2*tig;
                float2 b2 = *(const float2*)(bo + c);
                float2 v2;
                v2.x = acc[mt][nt][2*i  ] + b2.x;
                v2.y = acc[mt][nt][2*i+1] + b2.y;
                *(float2*)(out + (size_t)r*EMB + c) = v2;
            }
        }
}

// ---------------------------------------------------------------------------
extern "C" void kernel_launch(void* const* d_in, const int* in_sizes, int n_in,
                              void* d_out, int out_size)
{
    const float* keys    = (const float*)d_in[0];
    const float* queries = (const float*)d_in[1];
    /* values d_in[2] unused by the reference math */
    const int*   mask    = (const int*)d_in[3];
    const float* Wk      = (const float*)d_in[4];
    const float* Wq      = (const float*)d_in[5];
    const float* Wv      = (const float*)d_in[6];
    const float* Wo      = (const float*)d_in[7];
    const float* bo      = (const float*)d_in[8];
    float* out = (float*)d_out;

    cudaFuncSetAttribute(proj_kernel,
                         cudaFuncAttributeMaxDynamicSharedMemorySize,
                         PROJ_SMEM_BYTES);
    cudaFuncSetAttribute(attn_kernel,
                         cudaFuncAttributeMaxDynamicSharedMemorySize,
                         ATTN_SMEM_BYTES);

    cvt_w_small<<<16, 256>>>(Wq, Wk, Wv, mask);
    cvt_wo_kernel<<<1024, 256>>>(Wo);

    proj_kernel<<<NPAIR/128, 256, PROJ_SMEM_BYTES>>>(queries, keys);

    dim3 ag(SEQ/QT, NH, NBATCH);
    attn_kernel<<<ag, 256, ATTN_SMEM_BYTES>>>();

    dim3 gg(NTOK/128, EMB/128);
    out_gemm_kernel<<<gg, 256>>>(bo, out);
}

// round 6
// speedup vs baseline: 10.0131x; 1.0152x over previous
#include <cuda_runtime.h>
#include <cuda_fp16.h>
#include <cstdint>
#include <cstddef>

#define NBATCH 2
#define SEQ    2048
#define NH     16
#define HD     64
#define EMB    1024
#define NTOK   (NBATCH*SEQ)      /* 4096 */
#define NPAIR  (NTOK*NH)         /* 65536 token-head pairs */

// q pre-scale: log2(e)/sqrt(EMB) so softmax uses pure ex2
#define QSCALE 0.04508422008715254f

// Scratch (device globals — no allocation allowed)
__device__ __half g_qh[(size_t)NTOK*EMB];     // pre-scaled by log2e/32
__device__ __half g_kh[(size_t)NTOK*EMB];
__device__ __half g_vh[(size_t)NTOK*EMB];
__device__ __half g_attnh[(size_t)NTOK*EMB];
__device__ __half g_wqh[HD*HD];
__device__ __half g_wkh[HD*HD];
__device__ __half g_wvh[HD*HD];
__device__ __half g_woh[(size_t)EMB*EMB];
__device__ __half g_biash[NTOK];              // 0 or -inf per (n, kpos)

// ---------------------------------------------------------------------------
// helpers
// ---------------------------------------------------------------------------
__device__ __forceinline__ uint32_t pack_half2(float lo, float hi) {
    uint32_t u;
    asm("cvt.rn.f16x2.f32 %0, %1, %2;" : "=r"(u) : "f"(hi), "f"(lo));
    return u;
}
__device__ __forceinline__ uint32_t hadd2(uint32_t a, uint32_t b) {
    uint32_t d;
    asm("add.rn.f16x2 %0, %1, %2;" : "=r"(d) : "r"(a), "r"(b));
    return d;
}
__device__ __forceinline__ uint32_t ex2_f16x2(uint32_t a) {
    uint32_t d;
    asm("ex2.approx.f16x2 %0, %1;" : "=r"(d) : "r"(a));
    return d;
}
__device__ __forceinline__ void mma_f16(float* d,
                                        uint32_t a0, uint32_t a1,
                                        uint32_t a2, uint32_t a3,
                                        uint32_t b0, uint32_t b1) {
    asm volatile(
        "mma.sync.aligned.m16n8k16.row.col.f32.f16.f16.f32 "
        "{%0,%1,%2,%3}, {%4,%5,%6,%7}, {%8,%9}, {%0,%1,%2,%3};"
        : "+f"(d[0]), "+f"(d[1]), "+f"(d[2]), "+f"(d[3])
        : "r"(a0), "r"(a1), "r"(a2), "r"(a3), "r"(b0), "r"(b1));
}
// fp16-accumulator mma: C packed as 2x f16x2 (c0 = row g pair, c1 = row g+8)
__device__ __forceinline__ void mma_s16(uint32_t& c0, uint32_t& c1,
                                        uint32_t a0, uint32_t a1,
                                        uint32_t a2, uint32_t a3,
                                        uint32_t b0, uint32_t b1) {
    asm volatile(
        "mma.sync.aligned.m16n8k16.row.col.f16.f16.f16.f16 "
        "{%0,%1}, {%2,%3,%4,%5}, {%6,%7}, {%0,%1};"
        : "+r"(c0), "+r"(c1)
        : "r"(a0), "r"(a1), "r"(a2), "r"(a3), "r"(b0), "r"(b1));
}
__device__ __forceinline__ void cp16(void* dst_smem, const void* src) {
    uint32_t a = (uint32_t)__cvta_generic_to_shared(dst_smem);
    asm volatile("cp.async.cg.shared.global [%0], [%1], 16;" :: "r"(a), "l"(src));
}
#define CP_COMMIT() asm volatile("cp.async.commit_group;")
#define CP_WAIT0()  asm volatile("cp.async.wait_group 0;")

__device__ __forceinline__ void ldsm_x4(uint32_t& r0, uint32_t& r1,
                                        uint32_t& r2, uint32_t& r3,
                                        const void* smem_ptr) {
    uint32_t a = (uint32_t)__cvta_generic_to_shared(smem_ptr);
    asm volatile("ldmatrix.sync.aligned.m8n8.x4.shared.b16 "
                 "{%0,%1,%2,%3}, [%4];"
                 : "=r"(r0), "=r"(r1), "=r"(r2), "=r"(r3) : "r"(a));
}
__device__ __forceinline__ void ldsm_x4_t(uint32_t& r0, uint32_t& r1,
                                          uint32_t& r2, uint32_t& r3,
                                          const void* smem_ptr) {
    uint32_t a = (uint32_t)__cvta_generic_to_shared(smem_ptr);
    asm volatile("ldmatrix.sync.aligned.m8n8.x4.trans.shared.b16 "
                 "{%0,%1,%2,%3}, [%4];"
                 : "=r"(r0), "=r"(r1), "=r"(r2), "=r"(r3) : "r"(a));
}

// ---------------------------------------------------------------------------
// Weight / mask conversion prologue (fp32 -> fp16), run once per launch
// ---------------------------------------------------------------------------
__global__ __launch_bounds__(256) void cvt_wo_kernel(const float* __restrict__ Wo)
{
    int idx = blockIdx.x*256 + threadIdx.x;      // 262144 float4s
    float4 w = ((const float4*)Wo)[idx];
    uint2 p;
    p.x = pack_half2(w.x, w.y);
    p.y = pack_half2(w.z, w.w);
    ((uint2*)g_woh)[idx] = p;
}
__global__ __launch_bounds__(256) void cvt_w_small(
    const float* __restrict__ Wq, const float* __restrict__ Wk,
    const float* __restrict__ Wv, const int* __restrict__ mask)
{
    int idx = blockIdx.x*256 + threadIdx.x;      // 4096
    g_wqh[idx] = __float2half_rn(Wq[idx]);
    g_wkh[idx] = __float2half_rn(Wk[idx]);
    g_wvh[idx] = __float2half_rn(Wv[idx]);
    ((uint16_t*)g_biash)[idx] = mask[idx] ? 0x0000u : 0xFC00u;  // 0 / -inf
}

// ---------------------------------------------------------------------------
// Fused projection (fp16 mma): q = Xq Wq^T (scaled), v = q Wv^T (from frags),
// k = Xk Wk^T.  Block = 128 pairs, 256 threads (8 warps x 16 rows).
// ---------------------------------------------------------------------------
#define PROJ_SMEM_BYTES ((2*128*72 + 3*64*72)*2)

__global__ __launch_bounds__(256) void proj_kernel(
    const float* __restrict__ queries, const float* __restrict__ keys)
{
    extern __shared__ __half psm[];
    __half* xq_s = psm;                 // 128 x 72
    __half* xk_s = psm + 128*72;        // 128 x 72
    __half* wq_s = psm + 2*128*72;      // 64 x 72
    __half* wk_s = wq_s + 64*72;
    __half* wv_s = wk_s + 64*72;

    int tid  = threadIdx.x;
    int lane = tid & 31, warp = tid >> 5;
    int g = lane >> 2, tig = lane & 3;
    int r0 = warp * 16;
    size_t pb = (size_t)blockIdx.x * 128;

    #pragma unroll
    for (int it = 0; it < 2; it++) {
        int idx = tid + it*256;
        int r = idx >> 3, j = idx & 7;
        cp16(wq_s + r*72 + j*8, g_wqh + r*64 + j*8);
        cp16(wk_s + r*72 + j*8, g_wkh + r*64 + j*8);
        cp16(wv_s + r*72 + j*8, g_wvh + r*64 + j*8);
    }
    CP_COMMIT();
    #pragma unroll
    for (int it = 0; it < 8; it++) {
        int idx = tid + it*256;
        int r = idx >> 4, j = idx & 15;
        float4 a = *(const float4*)(queries + (pb + r)*64 + j*4);
        float4 b = *(const float4*)(keys    + (pb + r)*64 + j*4);
        uint2 pa, pk;
        pa.x = pack_half2(a.x, a.y); pa.y = pack_half2(a.z, a.w);
        pk.x = pack_half2(b.x, b.y); pk.y = pack_half2(b.z, b.w);
        *(uint2*)(xq_s + r*72 + j*4) = pa;
        *(uint2*)(xk_s + r*72 + j*4) = pk;
    }
    CP_WAIT0();
    __syncthreads();

    uint32_t aq[4][4], ak[4][4];
    #pragma unroll
    for (int ks = 0; ks < 4; ks++) {
        int k0 = ks*16;
        aq[ks][0] = *(const uint32_t*)(xq_s + (r0+g  )*72 + k0 + 2*tig);
        aq[ks][1] = *(const uint32_t*)(xq_s + (r0+g+8)*72 + k0 + 2*tig);
        aq[ks][2] = *(const uint32_t*)(xq_s + (r0+g  )*72 + k0 + 8 + 2*tig);
        aq[ks][3] = *(const uint32_t*)(xq_s + (r0+g+8)*72 + k0 + 8 + 2*tig);
        ak[ks][0] = *(const uint32_t*)(xk_s + (r0+g  )*72 + k0 + 2*tig);
        ak[ks][1] = *(const uint32_t*)(xk_s + (r0+g+8)*72 + k0 + 2*tig);
        ak[ks][2] = *(const uint32_t*)(xk_s + (r0+g  )*72 + k0 + 8 + 2*tig);
        ak[ks][3] = *(const uint32_t*)(xk_s + (r0+g+8)*72 + k0 + 8 + 2*tig);
    }

    float cq[8][4];
    #pragma unroll
    for (int nt = 0; nt < 8; nt++) { cq[nt][0]=cq[nt][1]=cq[nt][2]=cq[nt][3]=0.f; }
    #pragma unroll
    for (int ks = 0; ks < 4; ks++)
        #pragma unroll
        for (int nt = 0; nt < 8; nt++) {
            uint32_t b0 = *(const uint32_t*)(wq_s + (nt*8+g)*72 + ks*16 + 2*tig);
            uint32_t b1 = *(const uint32_t*)(wq_s + (nt*8+g)*72 + ks*16 + 8 + 2*tig);
            mma_f16(cq[nt], aq[ks][0], aq[ks][1], aq[ks][2], aq[ks][3], b0, b1);
        }

    float cv[8][4];
    #pragma unroll
    for (int nt = 0; nt < 8; nt++) { cv[nt][0]=cv[nt][1]=cv[nt][2]=cv[nt][3]=0.f; }
    #pragma unroll
    for (int ks = 0; ks < 4; ks++) {
        uint32_t a0 = pack_half2(cq[2*ks  ][0], cq[2*ks  ][1]);
        uint32_t a1 = pack_half2(cq[2*ks  ][2], cq[2*ks  ][3]);
        uint32_t a2 = pack_half2(cq[2*ks+1][0], cq[2*ks+1][1]);
        uint32_t a3 = pack_half2(cq[2*ks+1][2], cq[2*ks+1][3]);
        #pragma unroll
        for (int nt = 0; nt < 8; nt++) {
            uint32_t b0 = *(const uint32_t*)(wv_s + (nt*8+g)*72 + ks*16 + 2*tig);
            uint32_t b1 = *(const uint32_t*)(wv_s + (nt*8+g)*72 + ks*16 + 8 + 2*tig);
            mma_f16(cv[nt], a0, a1, a2, a3, b0, b1);
        }
    }

    #pragma unroll
    for (int nt = 0; nt < 8; nt++)
        #pragma unroll
        for (int i = 0; i < 2; i++) {
            int r = r0 + g + 8*i;
            *(uint32_t*)(g_qh + (pb + r)*64 + nt*8 + 2*tig) =
                pack_half2(cq[nt][2*i]*QSCALE, cq[nt][2*i+1]*QSCALE);
            *(uint32_t*)(g_vh + (pb + r)*64 + nt*8 + 2*tig) =
                pack_half2(cv[nt][2*i], cv[nt][2*i+1]);
        }

    float ck[8][4];
    #pragma unroll
    for (int nt = 0; nt < 8; nt++) { ck[nt][0]=ck[nt][1]=ck[nt][2]=ck[nt][3]=0.f; }
    #pragma unroll
    for (int ks = 0; ks < 4; ks++)
        #pragma unroll
        for (int nt = 0; nt < 8; nt++) {
            uint32_t b0 = *(const uint32_t*)(wk_s + (nt*8+g)*72 + ks*16 + 2*tig);
            uint32_t b1 = *(const uint32_t*)(wk_s + (nt*8+g)*72 + ks*16 + 8 + 2*tig);
            mma_f16(ck[nt], ak[ks][0], ak[ks][1], ak[ks][2], ak[ks][3], b0, b1);
        }
    #pragma unroll
    for (int nt = 0; nt < 8; nt++)
        #pragma unroll
        for (int i = 0; i < 2; i++) {
            int r = r0 + g + 8*i;
            *(uint32_t*)(g_kh + (pb + r)*64 + nt*8 + 2*tig) =
                pack_half2(ck[nt][2*i], ck[nt][2*i+1]);
        }
}

// ---------------------------------------------------------------------------
// Flash attention v3: 8 warps = 4 q-groups (32 rows) x 2 k-halves (32 cols).
// Halves K/V ldmatrix redundancy (4 warps share a K-half instead of 8 sharing
// the full tile). No max-tracking; l via ones-column mma; partial O/l summed
// across the two k-halves once at the end via smem (reusing dead K/V buffers).
// ---------------------------------------------------------------------------
#define QT 128
#define KST 72
#define NKT 32
#define RST 68   /* reduction row stride in floats */
#define ATTN_SMEM_BYTES ((128*KST + 2*64*KST + 2*64*KST + 2*64)*2 + 128*4)

__global__ __launch_bounds__(256, 2) void attn_kernel()
{
    extern __shared__ char smem_raw[];
    __half* q_s    = (__half*)smem_raw;       // 128 x 72
    __half* k_s    = q_s + 128*KST;           // 2 x 64 x 72
    __half* v_s    = k_s + 2*64*KST;          // 2 x 64 x 72
    __half* bias_s = v_s + 2*64*KST;          // 2 x 64
    float*  l_red  = (float*)(bias_s + 2*64); // 128 floats
    float*  red    = (float*)k_s;             // epilogue overlay (128 x RST)

    int tid  = threadIdx.x;
    int lane = tid & 31, warp = tid >> 5;
    int g = lane >> 2, tig = lane & 3;
    int wq = warp & 3, kh = warp >> 2;
    int r0 = wq * 32;
    int n = blockIdx.z, h = blockIdx.y, qt = blockIdx.x;

    const __half* qg    = g_qh + ((size_t)(n*SEQ + qt*QT)*NH + h)*HD;
    const __half* kbase = g_kh + ((size_t)(n*SEQ)*NH + h)*HD;
    const __half* vbase = g_vh + ((size_t)(n*SEQ)*NH + h)*HD;
    const __half* gbias = g_biash + n*SEQ;

    // ---- prolog: Q + K(0)/V(0) + bias(0), one group ----
    #pragma unroll
    for (int it = 0; it < 4; it++) {
        int idx = tid + it*256;
        int r = idx >> 3, j = idx & 7;
        cp16(q_s + r*KST + j*8, qg + (size_t)r*EMB + j*8);
    }
    #pragma unroll
    for (int it = 0; it < 2; it++) {
        int idx = tid + it*256;
        int c = idx >> 3, j = idx & 7;
        cp16(k_s + c*KST + j*8, kbase + (size_t)c*EMB + j*8);
        cp16(v_s + c*KST + j*8, vbase + (size_t)c*EMB + j*8);
    }
    if (tid < 8) cp16(bias_s + tid*8, gbias + tid*8);
    CP_COMMIT();

    // ---- per-lane ldmatrix bases ----
    // A-type (16x16): rows base+(lane&15), col (lane>>4)*8
    const __half* qldm = q_s + (size_t)(r0 + (lane & 15))*KST + ((lane >> 4) << 3);
    // B-type (16 kpos x 16 d): validated pattern from prior rounds
    int br = (lane & 7) + ((lane >> 4) << 3);
    int bc = ((lane >> 3) & 1) << 3;
    const __half* kldm_lane = k_s + (size_t)(kh*32 + br)*KST + bc;
    // V trans pattern
    int vr = ((lane >> 3) & 1)*8 + (lane & 7);
    int vc = (lane >> 4) * 8;
    const __half* vldm_lane = v_s + (size_t)(kh*32 + vr)*KST + vc;

    float o[2][8][4];
    float o8[2][4];
    #pragma unroll
    for (int mt = 0; mt < 2; mt++) {
        o8[mt][0]=o8[mt][1]=o8[mt][2]=o8[mt][3]=0.f;
        #pragma unroll
        for (int nt = 0; nt < 8; nt++)
            o[mt][nt][0]=o[mt][nt][1]=o[mt][nt][2]=o[mt][nt][3]=0.f;
    }
    uint32_t ones_b = (g == 0) ? 0x3C003C00u : 0u;

    for (int kt = 0; kt < NKT; kt++) {
        int cur = kt & 1;
        CP_WAIT0();
        __syncthreads();

        // prefetch next tile
        if (kt + 1 < NKT) {
            int nxt = cur ^ 1;
            const __half* kg = kbase + (size_t)(kt+1)*64*EMB;
            const __half* vg = vbase + (size_t)(kt+1)*64*EMB;
            #pragma unroll
            for (int it = 0; it < 2; it++) {
                int idx = tid + it*256;
                int c = idx >> 3, j = idx & 7;
                cp16(k_s + (nxt*64 + c)*KST + j*8, kg + (size_t)c*EMB + j*8);
                cp16(v_s + (nxt*64 + c)*KST + j*8, vg + (size_t)c*EMB + j*8);
            }
            if (tid < 8) cp16(bias_s + nxt*64 + tid*8, gbias + (kt+1)*64 + tid*8);
            CP_COMMIT();
        }

        // ---- S = Q K^T  (32 q-rows x 32 k-cols per warp, fp16 acc) ----
        uint32_t sc[2][4][2];
        #pragma unroll
        for (int mt = 0; mt < 2; mt++)
            #pragma unroll
            for (int nt = 0; nt < 4; nt++) { sc[mt][nt][0]=0u; sc[mt][nt][1]=0u; }

        const __half* kl = kldm_lane + (size_t)cur*64*KST;
        #pragma unroll
        for (int ks = 0; ks < 4; ks++) {
            uint32_t qa0[4], qa1[4];
            ldsm_x4(qa0[0], qa0[1], qa0[2], qa0[3], qldm + ks*16);
            ldsm_x4(qa1[0], qa1[1], qa1[2], qa1[3], qldm + 16*KST + ks*16);
            #pragma unroll
            for (int ntp = 0; ntp < 2; ntp++) {
                uint32_t b0a, b1a, b0b, b1b;
                ldsm_x4(b0a, b1a, b0b, b1b, kl + (size_t)ntp*16*KST + ks*16);
                mma_s16(sc[0][2*ntp  ][0], sc[0][2*ntp  ][1],
                        qa0[0], qa0[1], qa0[2], qa0[3], b0a, b1a);
                mma_s16(sc[0][2*ntp+1][0], sc[0][2*ntp+1][1],
                        qa0[0], qa0[1], qa0[2], qa0[3], b0b, b1b);
                mma_s16(sc[1][2*ntp  ][0], sc[1][2*ntp  ][1],
                        qa1[0], qa1[1], qa1[2], qa1[3], b0a, b1a);
                mma_s16(sc[1][2*ntp+1][0], sc[1][2*ntp+1][1],
                        qa1[0], qa1[1], qa1[2], qa1[3], b0b, b1b);
            }
        }

        // ---- p = 2^(s + bias) in place ----
        const __half* bb_base = bias_s + cur*64 + kh*32;
        #pragma unroll
        for (int nt = 0; nt < 4; nt++) {
            uint32_t bb = *(const uint32_t*)(bb_base + nt*8 + 2*tig);
            sc[0][nt][0] = ex2_f16x2(hadd2(sc[0][nt][0], bb));
            sc[0][nt][1] = ex2_f16x2(hadd2(sc[0][nt][1], bb));
            sc[1][nt][0] = ex2_f16x2(hadd2(sc[1][nt][0], bb));
            sc[1][nt][1] = ex2_f16x2(hadd2(sc[1][nt][1], bb));
        }

        // ---- O += P V ; l += P*ones  ----
        const __half* vl = vldm_lane + (size_t)cur*64*KST;
        #pragma unroll
        for (int kc = 0; kc < 2; kc++) {
            uint32_t a00 = sc[0][2*kc][0],   a01 = sc[0][2*kc][1];
            uint32_t a02 = sc[0][2*kc+1][0], a03 = sc[0][2*kc+1][1];
            uint32_t a10 = sc[1][2*kc][0],   a11 = sc[1][2*kc][1];
            uint32_t a12 = sc[1][2*kc+1][0], a13 = sc[1][2*kc+1][1];
            #pragma unroll
            for (int ntp = 0; ntp < 4; ntp++) {
                uint32_t b0a, b1a, b0b, b1b;
                ldsm_x4_t(b0a, b1a, b0b, b1b, vl + (size_t)kc*16*KST + ntp*16);
                mma_f16(o[0][2*ntp  ], a00, a01, a02, a03, b0a, b1a);
                mma_f16(o[0][2*ntp+1], a00, a01, a02, a03, b0b, b1b);
                mma_f16(o[1][2*ntp  ], a10, a11, a12, a13, b0a, b1a);
                mma_f16(o[1][2*ntp+1], a10, a11, a12, a13, b0b, b1b);
            }
            mma_f16(o8[0], a00, a01, a02, a03, ones_b, ones_b);
            mma_f16(o8[1], a10, a11, a12, a13, ones_b, ones_b);
        }
    }

    // ---- cross-half reduction via smem (k_s/v_s are dead now) ----
    __syncthreads();
    if (kh == 1) {
        #pragma unroll
        for (int mt = 0; mt < 2; mt++) {
            int row = r0 + mt*16 + g;
            #pragma unroll
            for (int nt = 0; nt < 8; nt++) {
                float2 v2a; v2a.x = o[mt][nt][0]; v2a.y = o[mt][nt][1];
                float2 v2b; v2b.x = o[mt][nt][2]; v2b.y = o[mt][nt][3];
                *(float2*)(red + (size_t)row*RST + nt*8 + 2*tig) = v2a;
                *(float2*)(red + (size_t)(row+8)*RST + nt*8 + 2*tig) = v2b;
            }
            if (tig == 0) {
                l_red[row]   = o8[mt][0];
                l_red[row+8] = o8[mt][2];
            }
        }
    }
    __syncthreads();
    if (kh == 0) {
        __half* og = g_attnh + ((size_t)(n*SEQ + qt*QT)*NH + h)*HD;
        int qb = lane & ~3;
        #pragma unroll
        for (int mt = 0; mt < 2; mt++) {
            int row = r0 + mt*16 + g;
            float l0 = __shfl_sync(0xffffffffu, o8[mt][0], qb) + l_red[row];
            float l1 = __shfl_sync(0xffffffffu, o8[mt][2], qb) + l_red[row+8];
            float inv0 = 1.f / l0, inv1 = 1.f / l1;
            #pragma unroll
            for (int nt = 0; nt < 8; nt++) {
                float2 ra = *(const float2*)(red + (size_t)row*RST + nt*8 + 2*tig);
                float2 rb = *(const float2*)(red + (size_t)(row+8)*RST + nt*8 + 2*tig);
                *(uint32_t*)(og + (size_t)row*EMB + nt*8 + 2*tig) =
                    pack_half2((o[mt][nt][0] + ra.x)*inv0,
                               (o[mt][nt][1] + ra.y)*inv0);
                *(uint32_t*)(og + (size_t)(row+8)*EMB + nt*8 + 2*tig) =
                    pack_half2((o[mt][nt][2] + rb.x)*inv1,
                               (o[mt][nt][3] + rb.y)*inv1);
            }
        }
    }
}

// ---------------------------------------------------------------------------
// Output projection: out = attn @ Wo^T + bo. fp16 mma, 128x128 tile,
// kblk=32, cp.async double-buffered. 8 warps (4m x 2n), warp tile 32x64.
// ---------------------------------------------------------------------------
__global__ __launch_bounds__(256) void out_gemm_kernel(
    const float* __restrict__ bo, float* __restrict__ out)
{
    __shared__ __half a_s[2][128*40];
    __shared__ __half w_s[2][128*40];

    int tid  = threadIdx.x;
    int lane = tid & 31, warp = tid >> 5;
    int g = lane >> 2, tig = lane & 3;
    int warp_m = warp & 3, warp_n = warp >> 2;
    int r0 = warp_m * 32;
    int c0 = warp_n * 64;
    int bt = blockIdx.x;
    int bq = blockIdx.y;

    const __half* gA = g_attnh + (size_t)bt*128*EMB;
    const __half* gW = g_woh   + (size_t)bq*128*EMB;

    float acc[2][8][4];
    #pragma unroll
    for (int mt = 0; mt < 2; mt++)
        #pragma unroll
        for (int nt = 0; nt < 8; nt++)
            acc[mt][nt][0]=acc[mt][nt][1]=acc[mt][nt][2]=acc[mt][nt][3]=0.f;

    {
        #pragma unroll
        for (int it = 0; it < 2; it++) {
            int idx = tid + it*256;
            int r = idx >> 2, j = idx & 3;
            cp16(&a_s[0][r*40 + j*8], gA + (size_t)r*EMB + j*8);
            cp16(&w_s[0][r*40 + j*8], gW + (size_t)r*EMB + j*8);
        }
        CP_COMMIT();
    }

    for (int kb = 0; kb < EMB/32; kb++) {
        int cur = kb & 1;
        CP_WAIT0();
        __syncthreads();
        if (kb + 1 < EMB/32) {
            int nxt = cur ^ 1;
            #pragma unroll
            for (int it = 0; it < 2; it++) {
                int idx = tid + it*256;
                int r = idx >> 2, j = idx & 3;
                cp16(&a_s[nxt][r*40 + j*8], gA + (size_t)r*EMB + (kb+1)*32 + j*8);
                cp16(&w_s[nxt][r*40 + j*8], gW + (size_t)r*EMB + (kb+1)*32 + j*8);
            }
            CP_COMMIT();
        }

        const __half* ac = a_s[cur];
        const __half* wc = w_s[cur];
        #pragma unroll
        for (int ks = 0; ks < 2; ks++) {
            int k0 = ks*16;
            uint32_t a0[4], a1[4];
            a0[0] = *(const uint32_t*)(ac + (r0+g   )*40 + k0 + 2*tig);
            a0[1] = *(const uint32_t*)(ac + (r0+g+8 )*40 + k0 + 2*tig);
            a0[2] = *(const uint32_t*)(ac + (r0+g   )*40 + k0 + 8 + 2*tig);
            a0[3] = *(const uint32_t*)(ac + (r0+g+8 )*40 + k0 + 8 + 2*tig);
            a1[0] = *(const uint32_t*)(ac + (r0+g+16)*40 + k0 + 2*tig);
            a1[1] = *(const uint32_t*)(ac + (r0+g+24)*40 + k0 + 2*tig);
            a1[2] = *(const uint32_t*)(ac + (r0+g+16)*40 + k0 + 8 + 2*tig);
            a1[3] = *(const uint32_t*)(ac + (r0+g+24)*40 + k0 + 8 + 2*tig);
            #pragma unroll
            for (int nt = 0; nt < 8; nt++) {
                uint32_t b0 = *(const uint32_t*)(wc + (c0+nt*8+g)*40 + k0 + 2*tig);
                uint32_t b1 = *(const uint32_t*)(wc + (c0+nt*8+g)*40 + k0 + 8 + 2*tig);
                mma_f16(acc[0][nt], a0[0], a0[1], a0[2], a0[3], b0, b1);
                mma_f16(acc[1][nt], a1[0], a1[1], a1[2], a1[3], b0, b1);
            }
        }
    }

    #pragma unroll
    for (int mt = 0; mt < 2; mt++)
        #pragma unroll
        for (int i = 0; i < 2; i++) {
            int r = bt*128 + r0 + mt*16 + g + 8*i;
            #pragma unroll
            for (int nt = 0; nt < 8; nt++) {
                int c = bq*128 + c0 + nt*8 + 2*tig;
                float2 b2 = *(const float2*)(bo + c);
                float2 v2;
                v2.x = acc[mt][nt][2*i  ] + b2.x;
                v2.y = acc[mt][nt][2*i+1] + b2.y;
                *(float2*)(out + (size_t)r*EMB + c) = v2;
            }
        }
}

// ---------------------------------------------------------------------------
extern "C" void kernel_launch(void* const* d_in, const int* in_sizes, int n_in,
                              void* d_out, int out_size)
{
    const float* keys    = (const float*)d_in[0];
    const float* queries = (const float*)d_in[1];
    /* values d_in[2] unused by the reference math */
    const int*   mask    = (const int*)d_in[3];
    const float* Wk      = (const float*)d_in[4];
    const float* Wq      = (const float*)d_in[5];
    const float* Wv      = (const float*)d_in[6];
    const float* Wo      = (const float*)d_in[7];
    const float* bo      = (const float*)d_in[8];
    float* out = (float*)d_out;

    cudaFuncSetAttribute(proj_kernel,
                         cudaFuncAttributeMaxDynamicSharedMemorySize,
                         PROJ_SMEM_BYTES);
    cudaFuncSetAttribute(attn_kernel,
                         cudaFuncAttributeMaxDynamicSharedMemorySize,
                         ATTN_SMEM_BYTES);

    cvt_w_small<<<16, 256>>>(Wq, Wk, Wv, mask);
    cvt_wo_kernel<<<1024, 256>>>(Wo);

    proj_kernel<<<NPAIR/128, 256, PROJ_SMEM_BYTES>>>(queries, keys);

    dim3 ag(SEQ/QT, NH, NBATCH);
    attn_kernel<<<ag, 256, ATTN_SMEM_BYTES>>>();

    dim3 gg(NTOK/128, EMB/128);
    out_gemm_kernel<<<gg, 256>>>(bo, out);
}